// round 1
// baseline (speedup 1.0000x reference)
#include <cuda_runtime.h>
#include <cstdint>

#define DEV __device__ __forceinline__

// ---------------- packed f32x2 helpers (FFMA2 path, sm_100+) ----------------
DEV unsigned long long pack2(float lo, float hi) {
    unsigned long long r;
    asm("mov.b64 %0, {%1, %2};" : "=l"(r) : "f"(lo), "f"(hi));
    return r;
}
DEV void unpack2(unsigned long long v, float& lo, float& hi) {
    asm("mov.b64 {%0, %1}, %2;" : "=f"(lo), "=f"(hi) : "l"(v));
}
DEV unsigned long long fma2(unsigned long long a, unsigned long long b, unsigned long long c) {
    unsigned long long d;
    asm("fma.rn.f32x2 %0, %1, %2, %3;" : "=l"(d) : "l"(a), "l"(b), "l"(c));
    return d;
}

constexpr int TPB   = 256;   // 8 warps
constexpr int WARPS = 8;
constexpr int EPW   = 8;     // edges per warp per tile
constexpr int EPB   = WARPS * EPW;   // 64 edges per block-tile
constexpr float LN_EPS = 1e-5f;

// Shared memory layout (bytes)
constexpr int OFF_W1P  = 0;                    // 128 kp x 128 j x 8B = 131072
constexpr int OFF_H    = 131072;               // 8 warps x 8 edges x 256 f = 65536
constexpr int OFF_G    = OFF_H + 65536;        // gamma 256 f
constexpr int OFF_BETA = OFF_G + 1024;         // beta  256 f
constexpr int OFF_B1   = OFF_BETA + 1024;      // b1    128 f
constexpr int OFF_W2   = OFF_B1 + 512;         // W2    128 f
constexpr int SMEM_TOTAL = OFF_W2 + 512;       // 199680 B

__global__ __launch_bounds__(TPB, 1)
void edge_mlp_kernel(const float* __restrict__ x,
                     const int*   __restrict__ src,
                     const int*   __restrict__ dst,
                     const float* __restrict__ a,
                     const float* __restrict__ W1,
                     const float* __restrict__ b1,
                     const float* __restrict__ W2,
                     const float* __restrict__ b2,
                     const float* __restrict__ gamma,
                     const float* __restrict__ beta,
                     float* __restrict__ out,
                     int E)
{
    extern __shared__ char smem[];
    unsigned long long* W1p = reinterpret_cast<unsigned long long*>(smem + OFF_W1P);
    float* hbuf = reinterpret_cast<float*>(smem + OFF_H);
    float* sg   = reinterpret_cast<float*>(smem + OFF_G);
    float* sbt  = reinterpret_cast<float*>(smem + OFF_BETA);
    float* sb1  = reinterpret_cast<float*>(smem + OFF_B1);
    float* sw2  = reinterpret_cast<float*>(smem + OFF_W2);

    const int tid = threadIdx.x;

    // ---- Stage W1 into SMEM as k-pair float2s: W1p[kp*128+j] = (W1[2kp][j], W1[2kp+1][j])
    for (int i = tid; i < 128 * 128; i += TPB) {
        int kp = i >> 7, j = i & 127;
        W1p[i] = pack2(__ldg(W1 + (2 * kp) * 128 + j), __ldg(W1 + (2 * kp + 1) * 128 + j));
    }
    for (int i = tid; i < 256; i += TPB) { sg[i] = __ldg(gamma + i); sbt[i] = __ldg(beta + i); }
    if (tid < 128) { sb1[tid] = __ldg(b1 + tid); sw2[tid] = __ldg(W2 + tid); }
    __syncthreads();

    const float b2v = __ldg(b2);
    const int warp = tid >> 5;
    const int lane = tid & 31;
    float* hw = hbuf + warp * (EPW * 256);
    const int g0 = lane * 4;

    // Per-lane constant slices (live across the whole loop; cheap in regs)
    const float4 g_lo  = *reinterpret_cast<const float4*>(sg  + g0);
    const float4 g_hi  = *reinterpret_cast<const float4*>(sg  + 128 + g0);
    const float4 bt_lo = *reinterpret_cast<const float4*>(sbt + g0);
    const float4 bt_hi = *reinterpret_cast<const float4*>(sbt + 128 + g0);
    const float4 b14   = *reinterpret_cast<const float4*>(sb1 + g0);
    const float4 w24   = *reinterpret_cast<const float4*>(sw2 + g0);

    const int ntiles = (E + EPB - 1) / EPB;
    for (int t = blockIdx.x; t < ntiles; t += gridDim.x) {
        const int ebase = t * EPB + warp * EPW;

        // ---------------- Phase A: gather + scale ----------------
        float4 vs[EPW], vd[EPW];
        float  av[EPW];
        #pragma unroll
        for (int e = 0; e < EPW; e++) {
            int ei = min(ebase + e, E - 1);           // clamp; store is guarded
            int si = __ldg(src + ei);
            int di = __ldg(dst + ei);
            av[e]  = __ldg(a + ei);
            vs[e]  = __ldg(reinterpret_cast<const float4*>(x + (size_t)si * 128) + lane);
            vd[e]  = __ldg(reinterpret_cast<const float4*>(x + (size_t)di * 128) + lane);
        }

        // ---------------- LayerNorm (per edge over 256) + write h to SMEM ---
        #pragma unroll
        for (int e = 0; e < EPW; e++) {
            const float ae = av[e];
            float4 s4 = vs[e], d4 = vd[e];
            s4.x *= ae; s4.y *= ae; s4.z *= ae; s4.w *= ae;
            d4.x *= ae; d4.y *= ae; d4.z *= ae; d4.w *= ae;

            float sum = (s4.x + s4.y) + (s4.z + s4.w) + (d4.x + d4.y) + (d4.z + d4.w);
            float sq = s4.x * s4.x;
            sq = fmaf(s4.y, s4.y, sq); sq = fmaf(s4.z, s4.z, sq); sq = fmaf(s4.w, s4.w, sq);
            sq = fmaf(d4.x, d4.x, sq); sq = fmaf(d4.y, d4.y, sq);
            sq = fmaf(d4.z, d4.z, sq); sq = fmaf(d4.w, d4.w, sq);
            #pragma unroll
            for (int o = 16; o > 0; o >>= 1) {
                sum += __shfl_xor_sync(0xffffffffu, sum, o);
                sq  += __shfl_xor_sync(0xffffffffu, sq,  o);
            }
            const float mu   = sum * (1.0f / 256.0f);
            const float var  = fmaf(-mu, mu, sq * (1.0f / 256.0f));
            const float rstd = rsqrtf(var + LN_EPS);

            float4 n0, n1;
            n0.x = fmaf((s4.x - mu) * rstd, g_lo.x, bt_lo.x);
            n0.y = fmaf((s4.y - mu) * rstd, g_lo.y, bt_lo.y);
            n0.z = fmaf((s4.z - mu) * rstd, g_lo.z, bt_lo.z);
            n0.w = fmaf((s4.w - mu) * rstd, g_lo.w, bt_lo.w);
            n1.x = fmaf((d4.x - mu) * rstd, g_hi.x, bt_hi.x);
            n1.y = fmaf((d4.y - mu) * rstd, g_hi.y, bt_hi.y);
            n1.z = fmaf((d4.z - mu) * rstd, g_hi.z, bt_hi.z);
            n1.w = fmaf((d4.w - mu) * rstd, g_hi.w, bt_hi.w);
            *reinterpret_cast<float4*>(hw + e * 256 + g0)       = n0;
            *reinterpret_cast<float4*>(hw + e * 256 + 128 + g0) = n1;
        }
        __syncwarp();

        // ---------------- Phase B: h @ W1 via packed FFMA2 ----------------
        // Lane owns output cols j = lane*4 .. lane*4+3 for its warp's 8 edges.
        unsigned long long acc[EPW][4];
        #pragma unroll
        for (int e = 0; e < EPW; e++) {
            #pragma unroll
            for (int c = 0; c < 4; c++) acc[e][c] = 0ULL;  // (0.f, 0.f)
        }

        const unsigned long long* hp   = reinterpret_cast<const unsigned long long*>(hw);
        const unsigned long long* wrow = W1p + g0;
        #pragma unroll 2
        for (int kp = 0; kp < 128; kp++) {
            const ulonglong2 wA = *reinterpret_cast<const ulonglong2*>(wrow + (size_t)kp * 128);
            const ulonglong2 wB = *reinterpret_cast<const ulonglong2*>(wrow + (size_t)kp * 128 + 2);
            #pragma unroll
            for (int e = 0; e < EPW; e++) {
                const unsigned long long h2 = hp[e * 128 + kp];  // (h[2kp], h[2kp+1]) broadcast
                acc[e][0] = fma2(h2, wA.x, acc[e][0]);
                acc[e][1] = fma2(h2, wA.y, acc[e][1]);
                acc[e][2] = fma2(h2, wB.x, acc[e][2]);
                acc[e][3] = fma2(h2, wB.y, acc[e][3]);
            }
        }

        // ---------------- Epilogue: bias + ELU + dot(W2) + reduce ----------
        #pragma unroll
        for (int e = 0; e < EPW; e++) {
            float lo, hi, p = 0.0f;
            unpack2(acc[e][0], lo, hi);
            float v0 = lo + hi + b14.x; v0 = v0 > 0.0f ? v0 : (__expf(v0) - 1.0f);
            p = fmaf(v0, w24.x, p);
            unpack2(acc[e][1], lo, hi);
            float v1 = lo + hi + b14.y; v1 = v1 > 0.0f ? v1 : (__expf(v1) - 1.0f);
            p = fmaf(v1, w24.y, p);
            unpack2(acc[e][2], lo, hi);
            float v2 = lo + hi + b14.z; v2 = v2 > 0.0f ? v2 : (__expf(v2) - 1.0f);
            p = fmaf(v2, w24.z, p);
            unpack2(acc[e][3], lo, hi);
            float v3 = lo + hi + b14.w; v3 = v3 > 0.0f ? v3 : (__expf(v3) - 1.0f);
            p = fmaf(v3, w24.w, p);
            #pragma unroll
            for (int o = 16; o > 0; o >>= 1) p += __shfl_xor_sync(0xffffffffu, p, o);
            const int ei = ebase + e;
            if (lane == 0 && ei < E) out[ei] = p + b2v;
        }
        __syncwarp();   // hbuf reuse guard for next tile
    }
}

extern "C" void kernel_launch(void* const* d_in, const int* in_sizes, int n_in,
                              void* d_out, int out_size)
{
    const float* x     = (const float*)d_in[0];
    const int*   src   = (const int*)  d_in[1];
    const int*   dst   = (const int*)  d_in[2];
    const float* a     = (const float*)d_in[3];
    const float* W1    = (const float*)d_in[4];
    const float* b1    = (const float*)d_in[5];
    const float* W2    = (const float*)d_in[6];
    const float* b2    = (const float*)d_in[7];
    const float* gamma = (const float*)d_in[8];
    const float* beta  = (const float*)d_in[9];
    float* out = (float*)d_out;
    const int E = in_sizes[1];   // src element count = number of edges

    cudaFuncSetAttribute(edge_mlp_kernel,
                         cudaFuncAttributeMaxDynamicSharedMemorySize, SMEM_TOTAL);
    edge_mlp_kernel<<<148, TPB, SMEM_TOTAL>>>(x, src, dst, a, W1, b1, W2, b2,
                                              gamma, beta, out, E);
}

// round 4
// speedup vs baseline: 2.1190x; 2.1190x over previous
#include <cuda_runtime.h>
#include <cuda_bf16.h>
#include <cstdint>

#define DEV __device__ __forceinline__

DEV uint32_t smem_u32(const void* p) {
    uint32_t a;
    asm("{ .reg .u64 t; cvta.to.shared.u64 t, %1; cvt.u32.u64 %0, t; }" : "=r"(a) : "l"(p));
    return a;
}

DEV void ldmatrix_x4(uint32_t& r0, uint32_t& r1, uint32_t& r2, uint32_t& r3, uint32_t addr) {
    asm volatile("ldmatrix.sync.aligned.m8n8.x4.shared.b16 {%0,%1,%2,%3}, [%4];"
                 : "=r"(r0), "=r"(r1), "=r"(r2), "=r"(r3) : "r"(addr));
}

DEV void mma_bf16(float* d, uint32_t a0, uint32_t a1, uint32_t a2, uint32_t a3,
                  uint32_t b0, uint32_t b1) {
    asm volatile("mma.sync.aligned.m16n8k16.row.col.f32.bf16.bf16.f32 "
                 "{%0,%1,%2,%3}, {%4,%5,%6,%7}, {%8,%9}, {%0,%1,%2,%3};"
                 : "+f"(d[0]), "+f"(d[1]), "+f"(d[2]), "+f"(d[3])
                 : "r"(a0), "r"(a1), "r"(a2), "r"(a3), "r"(b0), "r"(b1));
}

DEV void split2(float a, float b, uint32_t& hi, uint32_t& lo) {
    __nv_bfloat16 ah = __float2bfloat16(a);
    __nv_bfloat16 bh = __float2bfloat16(b);
    float ar = a - __bfloat162float(ah);
    float br = b - __bfloat162float(bh);
    __nv_bfloat16 al = __float2bfloat16(ar);
    __nv_bfloat16 bl = __float2bfloat16(br);
    hi = (uint32_t)__bfloat16_as_ushort(ah) | ((uint32_t)__bfloat16_as_ushort(bh) << 16);
    lo = (uint32_t)__bfloat16_as_ushort(al) | ((uint32_t)__bfloat16_as_ushort(bl) << 16);
}

constexpr int TPB    = 256;     // 8 warps
constexpr int EPW    = 8;       // edges per warp (LN phase)
constexpr int M_TILE = 64;      // edges per block-tile
constexpr float LN_EPS = 1e-5f;

// Row stride for staged matrices: 256 bf16 + 8 pad = 264 bf16 = 528 bytes
constexpr int RSTRIDE = 528;

// SMEM layout (bytes)
constexpr int OFF_WHI  = 0;                        // W1^T hi: 128 rows x 528 B = 67584
constexpr int OFF_WLO  = OFF_WHI + 128 * RSTRIDE;  // 67584
constexpr int OFF_AH   = OFF_WLO + 128 * RSTRIDE;  // A hi: 64 rows x 528 = 33792
constexpr int OFF_AL   = OFF_AH + 64 * RSTRIDE;
constexpr int OFF_PB   = OFF_AL + 64 * RSTRIDE;    // pbuf 64 f
constexpr int OFF_SB1  = OFF_PB + 256;             // b1 128 f
constexpr int OFF_SW2  = OFF_SB1 + 512;            // W2 128 f
constexpr int OFF_G    = OFF_SW2 + 512;            // gamma 256 f
constexpr int OFF_BETA = OFF_G + 1024;             // beta 256 f
constexpr int SMEM_TOTAL = OFF_BETA + 1024;        // 206080

__global__ __launch_bounds__(TPB, 1)
void edge_mlp_hmma_kernel(const float* __restrict__ x,
                          const int*   __restrict__ src,
                          const int*   __restrict__ dst,
                          const float* __restrict__ a,
                          const float* __restrict__ W1,
                          const float* __restrict__ b1,
                          const float* __restrict__ W2,
                          const float* __restrict__ b2,
                          const float* __restrict__ gamma,
                          const float* __restrict__ beta,
                          float* __restrict__ out,
                          int E)
{
    extern __shared__ char smem[];
    float* pbuf = reinterpret_cast<float*>(smem + OFF_PB);
    float* sb1  = reinterpret_cast<float*>(smem + OFF_SB1);
    float* sw2  = reinterpret_cast<float*>(smem + OFF_SW2);
    float* sg   = reinterpret_cast<float*>(smem + OFF_G);
    float* sbt  = reinterpret_cast<float*>(smem + OFF_BETA);

    const int tid  = threadIdx.x;
    const int warp = tid >> 5;
    const int lane = tid & 31;

    // ---- Stage W1^T hi/lo into SMEM: Wt[j][k] at j*RSTRIDE + k*2
    for (int idx = tid; idx < 256 * 128; idx += TPB) {
        int k = idx >> 7, j = idx & 127;
        float w = __ldg(W1 + idx);
        __nv_bfloat16 wh = __float2bfloat16(w);
        __nv_bfloat16 wl = __float2bfloat16(w - __bfloat162float(wh));
        *reinterpret_cast<__nv_bfloat16*>(smem + OFF_WHI + j * RSTRIDE + k * 2) = wh;
        *reinterpret_cast<__nv_bfloat16*>(smem + OFF_WLO + j * RSTRIDE + k * 2) = wl;
    }
    for (int i = tid; i < 256; i += TPB) { sg[i] = __ldg(gamma + i); sbt[i] = __ldg(beta + i); }
    if (tid < 128) { sb1[tid] = __ldg(b1 + tid); sw2[tid] = __ldg(W2 + tid); }
    __syncthreads();

    const float b2v = __ldg(b2);
    const int g0 = lane * 4;
    const float4 g_lo  = *reinterpret_cast<const float4*>(sg  + g0);
    const float4 g_hi  = *reinterpret_cast<const float4*>(sg  + 128 + g0);
    const float4 bt_lo = *reinterpret_cast<const float4*>(sbt + g0);
    const float4 bt_hi = *reinterpret_cast<const float4*>(sbt + 128 + g0);

    // GEMM warp tiling: mbase = (warp/2)*16 edge rows; jbase = (warp&1)*64 output cols
    const int mbase = (warp >> 1) * 16;
    const int jbase = (warp & 1) * 64;

    // Per-lane ldmatrix address components
    const int arow  = (lane & 7) + ((lane >> 3) & 1) * 8;       // A frag row
    const int acolb = ((lane >> 4) & 1) * 16;                   // A frag col-half (bytes)
    const int brow  = (lane & 7) + ((lane >> 4) & 1) * 8;       // B frag row-in-pair
    const int bkb   = ((lane >> 3) & 1) * 16;                   // B frag k-half (bytes)

    const uint32_t sbase = smem_u32(smem);
    const uint32_t a_hi_addr = sbase + OFF_AH + (mbase + arow) * RSTRIDE + acolb;
    const uint32_t a_lo_addr = sbase + OFF_AL + (mbase + arow) * RSTRIDE + acolb;
    const uint32_t b_hi_addr = sbase + OFF_WHI + (jbase + brow) * RSTRIDE + bkb;
    const uint32_t b_lo_addr = sbase + OFF_WLO + (jbase + brow) * RSTRIDE + bkb;

    const int ntiles = (E + M_TILE - 1) / M_TILE;

    for (int t = blockIdx.x; t < ntiles; t += gridDim.x) {
        const int ebase = t * M_TILE;

        // ================= Phase A: gather + LN -> bf16 hi/lo staging =================
        {
            const int hbase = ebase + warp * EPW;
            float4 vs[EPW], vd[EPW];
            float  av[EPW];
            #pragma unroll
            for (int e = 0; e < EPW; e++) {
                int ei = min(hbase + e, E - 1);
                int si = __ldg(src + ei);
                int di = __ldg(dst + ei);
                av[e]  = __ldg(a + ei);
                vs[e]  = __ldg(reinterpret_cast<const float4*>(x + (size_t)si * 128) + lane);
                vd[e]  = __ldg(reinterpret_cast<const float4*>(x + (size_t)di * 128) + lane);
            }
            #pragma unroll
            for (int e = 0; e < EPW; e++) {
                const float ae = av[e];
                float4 s4 = vs[e], d4 = vd[e];
                s4.x *= ae; s4.y *= ae; s4.z *= ae; s4.w *= ae;
                d4.x *= ae; d4.y *= ae; d4.z *= ae; d4.w *= ae;

                float sum = (s4.x + s4.y) + (s4.z + s4.w) + (d4.x + d4.y) + (d4.z + d4.w);
                float sq = s4.x * s4.x;
                sq = fmaf(s4.y, s4.y, sq); sq = fmaf(s4.z, s4.z, sq); sq = fmaf(s4.w, s4.w, sq);
                sq = fmaf(d4.x, d4.x, sq); sq = fmaf(d4.y, d4.y, sq);
                sq = fmaf(d4.z, d4.z, sq); sq = fmaf(d4.w, d4.w, sq);
                #pragma unroll
                for (int o = 16; o > 0; o >>= 1) {
                    sum += __shfl_xor_sync(0xffffffffu, sum, o);
                    sq  += __shfl_xor_sync(0xffffffffu, sq,  o);
                }
                const float mu   = sum * (1.0f / 256.0f);
                const float var  = fmaf(-mu, mu, sq * (1.0f / 256.0f));
                const float rstd = rsqrtf(var + LN_EPS);

                float n0x = fmaf((s4.x - mu) * rstd, g_lo.x, bt_lo.x);
                float n0y = fmaf((s4.y - mu) * rstd, g_lo.y, bt_lo.y);
                float n0z = fmaf((s4.z - mu) * rstd, g_lo.z, bt_lo.z);
                float n0w = fmaf((s4.w - mu) * rstd, g_lo.w, bt_lo.w);
                float n1x = fmaf((d4.x - mu) * rstd, g_hi.x, bt_hi.x);
                float n1y = fmaf((d4.y - mu) * rstd, g_hi.y, bt_hi.y);
                float n1z = fmaf((d4.z - mu) * rstd, g_hi.z, bt_hi.z);
                float n1w = fmaf((d4.w - mu) * rstd, g_hi.w, bt_hi.w);

                uint32_t h0, l0, h1, l1, h2, l2, h3, l3;
                split2(n0x, n0y, h0, l0);
                split2(n0z, n0w, h1, l1);
                split2(n1x, n1y, h2, l2);
                split2(n1z, n1w, h3, l3);

                const int row = warp * EPW + e;
                char* Ah = smem + OFF_AH + row * RSTRIDE;
                char* Al = smem + OFF_AL + row * RSTRIDE;
                *reinterpret_cast<uint64_t*>(Ah + lane * 8)       = (uint64_t)h0 | ((uint64_t)h1 << 32);
                *reinterpret_cast<uint64_t*>(Ah + 256 + lane * 8) = (uint64_t)h2 | ((uint64_t)h3 << 32);
                *reinterpret_cast<uint64_t*>(Al + lane * 8)       = (uint64_t)l0 | ((uint64_t)l1 << 32);
                *reinterpret_cast<uint64_t*>(Al + 256 + lane * 8) = (uint64_t)l2 | ((uint64_t)l3 << 32);
            }
        }
        __syncthreads();

        // ================= Phase B: 3-term bf16 HMMA GEMM =================
        float d[8][4];
        #pragma unroll
        for (int n = 0; n < 8; n++) { d[n][0] = d[n][1] = d[n][2] = d[n][3] = 0.0f; }

        #pragma unroll 1
        for (int term = 0; term < 3; term++) {
            const uint32_t abase = (term == 1) ? a_lo_addr : a_hi_addr;
            const uint32_t bbase = (term == 2) ? b_lo_addr : b_hi_addr;
            #pragma unroll 4
            for (int kk = 0; kk < 16; kk++) {
                uint32_t a0, a1, a2, a3;
                ldmatrix_x4(a0, a1, a2, a3, abase + kk * 32);
                #pragma unroll
                for (int pr = 0; pr < 4; pr++) {
                    uint32_t r0, r1, r2, r3;
                    ldmatrix_x4(r0, r1, r2, r3, bbase + pr * 16 * RSTRIDE + kk * 32);
                    mma_bf16(d[2 * pr],     a0, a1, a2, a3, r0, r1);
                    mma_bf16(d[2 * pr + 1], a0, a1, a2, a3, r2, r3);
                }
            }
        }

        // ================= Epilogue: bias + ELU + dot(W2) =================
        float p0 = 0.0f, p1 = 0.0f;
        #pragma unroll
        for (int n = 0; n < 8; n++) {
            const int j0 = jbase + n * 8 + (lane & 3) * 2;
            const float bb0 = sb1[j0],     bb1 = sb1[j0 + 1];
            const float ww0 = sw2[j0],     ww1 = sw2[j0 + 1];
            float v;
            v = d[n][0] + bb0; v = v > 0.0f ? v : (__expf(v) - 1.0f); p0 = fmaf(v, ww0, p0);
            v = d[n][1] + bb1; v = v > 0.0f ? v : (__expf(v) - 1.0f); p0 = fmaf(v, ww1, p0);
            v = d[n][2] + bb0; v = v > 0.0f ? v : (__expf(v) - 1.0f); p1 = fmaf(v, ww0, p1);
            v = d[n][3] + bb1; v = v > 0.0f ? v : (__expf(v) - 1.0f); p1 = fmaf(v, ww1, p1);
        }
        p0 += __shfl_xor_sync(0xffffffffu, p0, 1);
        p0 += __shfl_xor_sync(0xffffffffu, p0, 2);
        p1 += __shfl_xor_sync(0xffffffffu, p1, 1);
        p1 += __shfl_xor_sync(0xffffffffu, p1, 2);

        const int r0 = mbase + (lane >> 2);
        const int r1 = r0 + 8;
        if ((warp & 1) == 1 && (lane & 3) == 0) {
            pbuf[r0] = p0;
            pbuf[r1] = p1;
        }
        __syncthreads();
        if ((warp & 1) == 0 && (lane & 3) == 0) {
            const int e0 = ebase + r0;
            const int e1 = ebase + r1;
            if (e0 < E) out[e0] = p0 + pbuf[r0] + b2v;
            if (e1 < E) out[e1] = p1 + pbuf[r1] + b2v;
        }
    }
}

extern "C" void kernel_launch(void* const* d_in, const int* in_sizes, int n_in,
                              void* d_out, int out_size)
{
    const float* x     = (const float*)d_in[0];
    const int*   src   = (const int*)  d_in[1];
    const int*   dst   = (const int*)  d_in[2];
    const float* a     = (const float*)d_in[3];
    const float* W1    = (const float*)d_in[4];
    const float* b1    = (const float*)d_in[5];
    const float* W2    = (const float*)d_in[6];
    const float* b2    = (const float*)d_in[7];
    const float* gamma = (const float*)d_in[8];
    const float* beta  = (const float*)d_in[9];
    float* out = (float*)d_out;
    const int E = in_sizes[1];

    cudaFuncSetAttribute(edge_mlp_hmma_kernel,
                         cudaFuncAttributeMaxDynamicSharedMemorySize, SMEM_TOTAL);
    edge_mlp_hmma_kernel<<<148, TPB, SMEM_TOTAL>>>(x, src, dst, a, W1, b1, W2, b2,
                                                   gamma, beta, out, E);
}

// round 5
// speedup vs baseline: 2.3446x; 1.1064x over previous
#include <cuda_runtime.h>
#include <cuda_bf16.h>
#include <cstdint>

#define DEV __device__ __forceinline__

DEV uint32_t smem_u32(const void* p) {
    uint32_t a;
    asm("{ .reg .u64 t; cvta.to.shared.u64 t, %1; cvt.u32.u64 %0, t; }" : "=r"(a) : "l"(p));
    return a;
}

DEV void ldmatrix_x4(uint32_t& r0, uint32_t& r1, uint32_t& r2, uint32_t& r3, uint32_t addr) {
    asm volatile("ldmatrix.sync.aligned.m8n8.x4.shared.b16 {%0,%1,%2,%3}, [%4];"
                 : "=r"(r0), "=r"(r1), "=r"(r2), "=r"(r3) : "r"(addr));
}

DEV void mma_bf16(float* d, uint32_t a0, uint32_t a1, uint32_t a2, uint32_t a3,
                  uint32_t b0, uint32_t b1) {
    asm volatile("mma.sync.aligned.m16n8k16.row.col.f32.bf16.bf16.f32 "
                 "{%0,%1,%2,%3}, {%4,%5,%6,%7}, {%8,%9}, {%0,%1,%2,%3};"
                 : "+f"(d[0]), "+f"(d[1]), "+f"(d[2]), "+f"(d[3])
                 : "r"(a0), "r"(a1), "r"(a2), "r"(a3), "r"(b0), "r"(b1));
}

DEV void split2(float a, float b, uint32_t& hi, uint32_t& lo) {
    __nv_bfloat16 ah = __float2bfloat16(a);
    __nv_bfloat16 bh = __float2bfloat16(b);
    float ar = a - __bfloat162float(ah);
    float br = b - __bfloat162float(bh);
    __nv_bfloat16 al = __float2bfloat16(ar);
    __nv_bfloat16 bl = __float2bfloat16(br);
    hi = (uint32_t)__bfloat16_as_ushort(ah) | ((uint32_t)__bfloat16_as_ushort(bh) << 16);
    lo = (uint32_t)__bfloat16_as_ushort(al) | ((uint32_t)__bfloat16_as_ushort(bl) << 16);
}

constexpr int TPB    = 256;     // 8 warps
constexpr int EPW    = 8;       // edges per warp (LN phase)
constexpr int M_TILE = 64;      // edges per block-tile
constexpr float LN_EPS = 1e-5f;

// Row stride for staged matrices: 256 bf16 + 8 pad = 264 bf16 = 528 bytes
constexpr int RSTRIDE = 528;

// SMEM layout (bytes)
constexpr int OFF_WHI  = 0;                        // W1^T hi: 128 rows x 528 B = 67584
constexpr int OFF_WLO  = OFF_WHI + 128 * RSTRIDE;  // 67584
constexpr int OFF_AH   = OFF_WLO + 128 * RSTRIDE;  // A hi: 64 rows x 528 = 33792
constexpr int OFF_AL   = OFF_AH + 64 * RSTRIDE;
constexpr int OFF_PB   = OFF_AL + 64 * RSTRIDE;    // pbuf 64 f
constexpr int OFF_SB1  = OFF_PB + 256;             // b1 128 f
constexpr int OFF_SW2  = OFF_SB1 + 512;            // W2 128 f
constexpr int OFF_G    = OFF_SW2 + 512;            // gamma 256 f
constexpr int OFF_BETA = OFF_G + 1024;             // beta 256 f
constexpr int SMEM_TOTAL = OFF_BETA + 1024;        // 206080

DEV void load_tile(int hbase, int E, int lane,
                   const int* __restrict__ src, const int* __restrict__ dst,
                   const float* __restrict__ a, const float* __restrict__ x,
                   float4* vs, float4* vd, float* av)
{
    #pragma unroll
    for (int e = 0; e < EPW; e++) {
        int ei = min(hbase + e, E - 1);
        int si = __ldg(src + ei);
        int di = __ldg(dst + ei);
        av[e]  = __ldg(a + ei);
        vs[e]  = __ldg(reinterpret_cast<const float4*>(x + (size_t)si * 128) + lane);
        vd[e]  = __ldg(reinterpret_cast<const float4*>(x + (size_t)di * 128) + lane);
    }
}

__global__ __launch_bounds__(TPB, 1)
void edge_mlp_hmma_kernel(const float* __restrict__ x,
                          const int*   __restrict__ src,
                          const int*   __restrict__ dst,
                          const float* __restrict__ a,
                          const float* __restrict__ W1,
                          const float* __restrict__ b1,
                          const float* __restrict__ W2,
                          const float* __restrict__ b2,
                          const float* __restrict__ gamma,
                          const float* __restrict__ beta,
                          float* __restrict__ out,
                          int E)
{
    extern __shared__ char smem[];
    float* pbuf = reinterpret_cast<float*>(smem + OFF_PB);
    float* sb1  = reinterpret_cast<float*>(smem + OFF_SB1);
    float* sw2  = reinterpret_cast<float*>(smem + OFF_SW2);
    float* sg   = reinterpret_cast<float*>(smem + OFF_G);
    float* sbt  = reinterpret_cast<float*>(smem + OFF_BETA);

    const int tid  = threadIdx.x;
    const int warp = tid >> 5;
    const int lane = tid & 31;

    // ---- Stage W1^T hi/lo into SMEM: Wt[j][k] at j*RSTRIDE + k*2
    for (int idx = tid; idx < 256 * 128; idx += TPB) {
        int k = idx >> 7, j = idx & 127;
        float w = __ldg(W1 + idx);
        __nv_bfloat16 wh = __float2bfloat16(w);
        __nv_bfloat16 wl = __float2bfloat16(w - __bfloat162float(wh));
        *reinterpret_cast<__nv_bfloat16*>(smem + OFF_WHI + j * RSTRIDE + k * 2) = wh;
        *reinterpret_cast<__nv_bfloat16*>(smem + OFF_WLO + j * RSTRIDE + k * 2) = wl;
    }
    for (int i = tid; i < 256; i += TPB) { sg[i] = __ldg(gamma + i); sbt[i] = __ldg(beta + i); }
    if (tid < 128) { sb1[tid] = __ldg(b1 + tid); sw2[tid] = __ldg(W2 + tid); }
    __syncthreads();

    const float b2v = __ldg(b2);
    const int g0 = lane * 4;
    const float4 g_lo  = *reinterpret_cast<const float4*>(sg  + g0);
    const float4 g_hi  = *reinterpret_cast<const float4*>(sg  + 128 + g0);
    const float4 bt_lo = *reinterpret_cast<const float4*>(sbt + g0);
    const float4 bt_hi = *reinterpret_cast<const float4*>(sbt + 128 + g0);

    // GEMM warp tiling: mbase = (warp/2)*16 edge rows; jbase = (warp&1)*64 output cols
    const int mbase = (warp >> 1) * 16;
    const int jbase = (warp & 1) * 64;

    // Per-lane ldmatrix address components
    const int arow  = (lane & 7) + ((lane >> 3) & 1) * 8;       // A frag row
    const int acolb = ((lane >> 4) & 1) * 16;                   // A frag col-half (bytes)
    const int brow  = (lane & 7) + ((lane >> 4) & 1) * 8;       // B frag row-in-pair
    const int bkb   = ((lane >> 3) & 1) * 16;                   // B frag k-half (bytes)

    const uint32_t sbase = smem_u32(smem);
    const uint32_t a_hi_addr = sbase + OFF_AH + (mbase + arow) * RSTRIDE + acolb;
    const uint32_t a_lo_addr = sbase + OFF_AL + (mbase + arow) * RSTRIDE + acolb;
    const uint32_t b_hi_addr = sbase + OFF_WHI + (jbase + brow) * RSTRIDE + bkb;
    const uint32_t b_lo_addr = sbase + OFF_WLO + (jbase + brow) * RSTRIDE + bkb;

    const int ntiles = (E + M_TILE - 1) / M_TILE;

    // -------- Gather prefetch pipeline --------
    float4 vs[EPW], vd[EPW];
    float  av[EPW];

    int t = blockIdx.x;
    if (t < ntiles)
        load_tile(t * M_TILE + warp * EPW, E, lane, src, dst, a, x, vs, vd, av);

    while (t < ntiles) {
        const int ebase = t * M_TILE;
        const int tn = t + gridDim.x;

        // ================= Phase A: LN (uses prefetched regs) -> staging =================
        #pragma unroll
        for (int e = 0; e < EPW; e++) {
            const float ae = av[e];
            float4 s4 = vs[e], d4 = vd[e];
            s4.x *= ae; s4.y *= ae; s4.z *= ae; s4.w *= ae;
            d4.x *= ae; d4.y *= ae; d4.z *= ae; d4.w *= ae;

            float sum = (s4.x + s4.y) + (s4.z + s4.w) + (d4.x + d4.y) + (d4.z + d4.w);
            float sq = s4.x * s4.x;
            sq = fmaf(s4.y, s4.y, sq); sq = fmaf(s4.z, s4.z, sq); sq = fmaf(s4.w, s4.w, sq);
            sq = fmaf(d4.x, d4.x, sq); sq = fmaf(d4.y, d4.y, sq);
            sq = fmaf(d4.z, d4.z, sq); sq = fmaf(d4.w, d4.w, sq);
            #pragma unroll
            for (int o = 16; o > 0; o >>= 1) {
                sum += __shfl_xor_sync(0xffffffffu, sum, o);
                sq  += __shfl_xor_sync(0xffffffffu, sq,  o);
            }
            const float mu   = sum * (1.0f / 256.0f);
            const float var  = fmaf(-mu, mu, sq * (1.0f / 256.0f));
            const float rstd = rsqrtf(var + LN_EPS);

            float n0x = fmaf((s4.x - mu) * rstd, g_lo.x, bt_lo.x);
            float n0y = fmaf((s4.y - mu) * rstd, g_lo.y, bt_lo.y);
            float n0z = fmaf((s4.z - mu) * rstd, g_lo.z, bt_lo.z);
            float n0w = fmaf((s4.w - mu) * rstd, g_lo.w, bt_lo.w);
            float n1x = fmaf((d4.x - mu) * rstd, g_hi.x, bt_hi.x);
            float n1y = fmaf((d4.y - mu) * rstd, g_hi.y, bt_hi.y);
            float n1z = fmaf((d4.z - mu) * rstd, g_hi.z, bt_hi.z);
            float n1w = fmaf((d4.w - mu) * rstd, g_hi.w, bt_hi.w);

            uint32_t h0, l0, h1, l1, h2, l2, h3, l3;
            split2(n0x, n0y, h0, l0);
            split2(n0z, n0w, h1, l1);
            split2(n1x, n1y, h2, l2);
            split2(n1z, n1w, h3, l3);

            const int row = warp * EPW + e;
            char* Ah = smem + OFF_AH + row * RSTRIDE;
            char* Al = smem + OFF_AL + row * RSTRIDE;
            *reinterpret_cast<uint64_t*>(Ah + lane * 8)       = (uint64_t)h0 | ((uint64_t)h1 << 32);
            *reinterpret_cast<uint64_t*>(Ah + 256 + lane * 8) = (uint64_t)h2 | ((uint64_t)h3 << 32);
            *reinterpret_cast<uint64_t*>(Al + lane * 8)       = (uint64_t)l0 | ((uint64_t)l1 << 32);
            *reinterpret_cast<uint64_t*>(Al + 256 + lane * 8) = (uint64_t)l2 | ((uint64_t)l3 << 32);
        }
        __syncthreads();

        // ---- Prefetch next tile's gathers; completes under the GEMM below ----
        if (tn < ntiles)
            load_tile(tn * M_TILE + warp * EPW, E, lane, src, dst, a, x, vs, vd, av);

        // ================= Phase B: merged 3-term bf16 HMMA GEMM =================
        float d[8][4];
        #pragma unroll
        for (int n = 0; n < 8; n++) { d[n][0] = d[n][1] = d[n][2] = d[n][3] = 0.0f; }

        #pragma unroll 2
        for (int kk = 0; kk < 16; kk++) {
            uint32_t ah0, ah1, ah2, ah3, al0, al1, al2, al3;
            ldmatrix_x4(ah0, ah1, ah2, ah3, a_hi_addr + kk * 32);
            ldmatrix_x4(al0, al1, al2, al3, a_lo_addr + kk * 32);
            #pragma unroll
            for (int pr = 0; pr < 4; pr++) {
                uint32_t bh0, bh1, bh2, bh3, bl0, bl1, bl2, bl3;
                ldmatrix_x4(bh0, bh1, bh2, bh3, b_hi_addr + pr * 16 * RSTRIDE + kk * 32);
                ldmatrix_x4(bl0, bl1, bl2, bl3, b_lo_addr + pr * 16 * RSTRIDE + kk * 32);
                mma_bf16(d[2 * pr],     ah0, ah1, ah2, ah3, bh0, bh1);
                mma_bf16(d[2 * pr + 1], ah0, ah1, ah2, ah3, bh2, bh3);
                mma_bf16(d[2 * pr],     al0, al1, al2, al3, bh0, bh1);
                mma_bf16(d[2 * pr + 1], al0, al1, al2, al3, bh2, bh3);
                mma_bf16(d[2 * pr],     ah0, ah1, ah2, ah3, bl0, bl1);
                mma_bf16(d[2 * pr + 1], ah0, ah1, ah2, ah3, bl2, bl3);
            }
        }

        // ================= Epilogue: bias + ELU + dot(W2) =================
        float p0 = 0.0f, p1 = 0.0f;
        #pragma unroll
        for (int n = 0; n < 8; n++) {
            const int j0 = jbase + n * 8 + (lane & 3) * 2;
            const float bb0 = sb1[j0],     bb1 = sb1[j0 + 1];
            const float ww0 = sw2[j0],     ww1 = sw2[j0 + 1];
            float v;
            v = d[n][0] + bb0; v = v > 0.0f ? v : (__expf(v) - 1.0f); p0 = fmaf(v, ww0, p0);
            v = d[n][1] + bb1; v = v > 0.0f ? v : (__expf(v) - 1.0f); p0 = fmaf(v, ww1, p0);
            v = d[n][2] + bb0; v = v > 0.0f ? v : (__expf(v) - 1.0f); p1 = fmaf(v, ww0, p1);
            v = d[n][3] + bb1; v = v > 0.0f ? v : (__expf(v) - 1.0f); p1 = fmaf(v, ww1, p1);
        }
        p0 += __shfl_xor_sync(0xffffffffu, p0, 1);
        p0 += __shfl_xor_sync(0xffffffffu, p0, 2);
        p1 += __shfl_xor_sync(0xffffffffu, p1, 1);
        p1 += __shfl_xor_sync(0xffffffffu, p1, 2);

        const int r0 = mbase + (lane >> 2);
        const int r1 = r0 + 8;
        if ((warp & 1) == 1 && (lane & 3) == 0) {
            pbuf[r0] = p0;
            pbuf[r1] = p1;
        }
        __syncthreads();
        if ((warp & 1) == 0 && (lane & 3) == 0) {
            const int e0 = ebase + r0;
            const int e1 = ebase + r1;
            if (e0 < E) out[e0] = p0 + pbuf[r0] + b2v;
            if (e1 < E) out[e1] = p1 + pbuf[r1] + b2v;
        }
        t = tn;
    }
}

extern "C" void kernel_launch(void* const* d_in, const int* in_sizes, int n_in,
                              void* d_out, int out_size)
{
    const float* x     = (const float*)d_in[0];
    const int*   src   = (const int*)  d_in[1];
    const int*   dst   = (const int*)  d_in[2];
    const float* a     = (const float*)d_in[3];
    const float* W1    = (const float*)d_in[4];
    const float* b1    = (const float*)d_in[5];
    const float* W2    = (const float*)d_in[6];
    const float* b2    = (const float*)d_in[7];
    const float* gamma = (const float*)d_in[8];
    const float* beta  = (const float*)d_in[9];
    float* out = (float*)d_out;
    const int E = in_sizes[1];

    cudaFuncSetAttribute(edge_mlp_hmma_kernel,
                         cudaFuncAttributeMaxDynamicSharedMemorySize, SMEM_TOTAL);
    edge_mlp_hmma_kernel<<<148, TPB, SMEM_TOTAL>>>(x, src, dst, a, W1, b1, W2, b2,
                                                   gamma, beta, out, E);
}

// round 6
// speedup vs baseline: 2.9682x; 1.2660x over previous
#include <cuda_runtime.h>
#include <cuda_fp16.h>
#include <cstdint>

#define DEV __device__ __forceinline__

DEV uint32_t smem_u32(const void* p) {
    uint32_t a;
    asm("{ .reg .u64 t; cvta.to.shared.u64 t, %1; cvt.u32.u64 %0, t; }" : "=r"(a) : "l"(p));
    return a;
}

DEV void ldmatrix_x4(uint32_t& r0, uint32_t& r1, uint32_t& r2, uint32_t& r3, uint32_t addr) {
    asm volatile("ldmatrix.sync.aligned.m8n8.x4.shared.b16 {%0,%1,%2,%3}, [%4];"
                 : "=r"(r0), "=r"(r1), "=r"(r2), "=r"(r3) : "r"(addr));
}

DEV void mma_f16(float* d, uint32_t a0, uint32_t a1, uint32_t a2, uint32_t a3,
                 uint32_t b0, uint32_t b1) {
    asm volatile("mma.sync.aligned.m16n8k16.row.col.f32.f16.f16.f32 "
                 "{%0,%1,%2,%3}, {%4,%5,%6,%7}, {%8,%9}, {%0,%1,%2,%3};"
                 : "+f"(d[0]), "+f"(d[1]), "+f"(d[2]), "+f"(d[3])
                 : "r"(a0), "r"(a1), "r"(a2), "r"(a3), "r"(b0), "r"(b1));
}

// fp16 hi/lo split of two floats, packed as (lo16|hi16) pairs
DEV void split2h(float a, float b, uint32_t& hi, uint32_t& lo) {
    __half ah = __float2half_rn(a);
    __half bh = __float2half_rn(b);
    float ar = a - __half2float(ah);
    float br = b - __half2float(bh);
    __half al = __float2half_rn(ar);
    __half bl = __float2half_rn(br);
    hi = (uint32_t)__half_as_ushort(ah) | ((uint32_t)__half_as_ushort(bh) << 16);
    lo = (uint32_t)__half_as_ushort(al) | ((uint32_t)__half_as_ushort(bl) << 16);
}

constexpr int TPB    = 384;     // 12 warps
constexpr int EPW    = 8;       // edges per warp (LN phase)
constexpr int M_TILE = 96;      // edges per block-tile (12 warps x 8)
constexpr float LN_EPS = 1e-5f;

// Row stride for staged matrices: 256 fp16 + 8 pad = 264 halves = 528 bytes
constexpr int RSTRIDE = 528;

// SMEM layout (bytes)
constexpr int OFF_W    = 0;                        // W1^T fp16: 128 rows x 528 B = 67584
constexpr int OFF_AH   = OFF_W + 128 * RSTRIDE;    // A hi: 96 rows x 528 = 50688
constexpr int OFF_AL   = OFF_AH + 96 * RSTRIDE;    // A lo: 50688
constexpr int OFF_PB   = OFF_AL + 96 * RSTRIDE;    // pbuf 96 f = 384
constexpr int OFF_SB1  = OFF_PB + 384;             // b1 128 f
constexpr int OFF_SW2  = OFF_SB1 + 512;            // W2 128 f
constexpr int OFF_G    = OFF_SW2 + 512;            // gamma 256 f
constexpr int OFF_BETA = OFF_G + 1024;             // beta 256 f
constexpr int SMEM_TOTAL = OFF_BETA + 1024;        // 172416

DEV void load_tile(int hbase, int E, int lane,
                   const int* __restrict__ src, const int* __restrict__ dst,
                   const float* __restrict__ a, const float* __restrict__ x,
                   float4* vs, float4* vd, float* av)
{
    #pragma unroll
    for (int e = 0; e < EPW; e++) {
        int ei = min(hbase + e, E - 1);
        int si = __ldg(src + ei);
        int di = __ldg(dst + ei);
        av[e]  = __ldg(a + ei);
        vs[e]  = __ldg(reinterpret_cast<const float4*>(x + (size_t)si * 128) + lane);
        vd[e]  = __ldg(reinterpret_cast<const float4*>(x + (size_t)di * 128) + lane);
    }
}

__global__ __launch_bounds__(TPB, 1)
void edge_mlp_hmma_kernel(const float* __restrict__ x,
                          const int*   __restrict__ src,
                          const int*   __restrict__ dst,
                          const float* __restrict__ a,
                          const float* __restrict__ W1,
                          const float* __restrict__ b1,
                          const float* __restrict__ W2,
                          const float* __restrict__ b2,
                          const float* __restrict__ gamma,
                          const float* __restrict__ beta,
                          float* __restrict__ out,
                          int E)
{
    extern __shared__ char smem[];
    float* pbuf = reinterpret_cast<float*>(smem + OFF_PB);
    float* sb1  = reinterpret_cast<float*>(smem + OFF_SB1);
    float* sw2  = reinterpret_cast<float*>(smem + OFF_SW2);
    float* sg   = reinterpret_cast<float*>(smem + OFF_G);
    float* sbt  = reinterpret_cast<float*>(smem + OFF_BETA);

    const int tid  = threadIdx.x;
    const int warp = tid >> 5;
    const int lane = tid & 31;

    // ---- Stage W1^T (single fp16) into SMEM: Wt[j][k] at j*RSTRIDE + k*2
    for (int idx = tid; idx < 256 * 128; idx += TPB) {
        int k = idx >> 7, j = idx & 127;
        float w = __ldg(W1 + idx);
        *reinterpret_cast<__half*>(smem + OFF_W + j * RSTRIDE + k * 2) = __float2half_rn(w);
    }
    for (int i = tid; i < 256; i += TPB) { sg[i] = __ldg(gamma + i); sbt[i] = __ldg(beta + i); }
    if (tid < 128) { sb1[tid] = __ldg(b1 + tid); sw2[tid] = __ldg(W2 + tid); }
    __syncthreads();

    const float b2v = __ldg(b2);
    const int g0 = lane * 4;
    const float4 g_lo  = *reinterpret_cast<const float4*>(sg  + g0);
    const float4 g_hi  = *reinterpret_cast<const float4*>(sg  + 128 + g0);
    const float4 bt_lo = *reinterpret_cast<const float4*>(sbt + g0);
    const float4 bt_hi = *reinterpret_cast<const float4*>(sbt + 128 + g0);

    // GEMM warp tiling: mbase = (warp/2)*16 edge rows; jbase = (warp&1)*64 output cols
    const int mbase = (warp >> 1) * 16;
    const int jbase = (warp & 1) * 64;

    // Per-lane ldmatrix address components
    const int arow  = (lane & 7) + ((lane >> 3) & 1) * 8;       // A frag row
    const int acolb = ((lane >> 4) & 1) * 16;                   // A frag col-half (bytes)
    const int brow  = (lane & 7) + ((lane >> 4) & 1) * 8;       // B frag row-in-pair
    const int bkb   = ((lane >> 3) & 1) * 16;                   // B frag k-half (bytes)

    const uint32_t sbase = smem_u32(smem);
    const uint32_t a_hi_addr = sbase + OFF_AH + (mbase + arow) * RSTRIDE + acolb;
    const uint32_t a_lo_addr = sbase + OFF_AL + (mbase + arow) * RSTRIDE + acolb;
    const uint32_t b_addr    = sbase + OFF_W  + (jbase + brow) * RSTRIDE + bkb;

    const int ntiles = (E + M_TILE - 1) / M_TILE;

    // -------- Gather prefetch pipeline --------
    float4 vs[EPW], vd[EPW];
    float  av[EPW];

    int t = blockIdx.x;
    if (t < ntiles)
        load_tile(t * M_TILE + warp * EPW, E, lane, src, dst, a, x, vs, vd, av);

    while (t < ntiles) {
        const int ebase = t * M_TILE;
        const int tn = t + gridDim.x;

        // ================= Phase A: LN (uses prefetched regs) -> staging =================
        #pragma unroll
        for (int e = 0; e < EPW; e++) {
            const float ae = av[e];
            float4 s4 = vs[e], d4 = vd[e];
            s4.x *= ae; s4.y *= ae; s4.z *= ae; s4.w *= ae;
            d4.x *= ae; d4.y *= ae; d4.z *= ae; d4.w *= ae;

            float sum = (s4.x + s4.y) + (s4.z + s4.w) + (d4.x + d4.y) + (d4.z + d4.w);
            float sq = s4.x * s4.x;
            sq = fmaf(s4.y, s4.y, sq); sq = fmaf(s4.z, s4.z, sq); sq = fmaf(s4.w, s4.w, sq);
            sq = fmaf(d4.x, d4.x, sq); sq = fmaf(d4.y, d4.y, sq);
            sq = fmaf(d4.z, d4.z, sq); sq = fmaf(d4.w, d4.w, sq);
            #pragma unroll
            for (int o = 16; o > 0; o >>= 1) {
                sum += __shfl_xor_sync(0xffffffffu, sum, o);
                sq  += __shfl_xor_sync(0xffffffffu, sq,  o);
            }
            const float mu   = sum * (1.0f / 256.0f);
            const float var  = fmaf(-mu, mu, sq * (1.0f / 256.0f));
            const float rstd = rsqrtf(var + LN_EPS);

            float n0x = fmaf((s4.x - mu) * rstd, g_lo.x, bt_lo.x);
            float n0y = fmaf((s4.y - mu) * rstd, g_lo.y, bt_lo.y);
            float n0z = fmaf((s4.z - mu) * rstd, g_lo.z, bt_lo.z);
            float n0w = fmaf((s4.w - mu) * rstd, g_lo.w, bt_lo.w);
            float n1x = fmaf((d4.x - mu) * rstd, g_hi.x, bt_hi.x);
            float n1y = fmaf((d4.y - mu) * rstd, g_hi.y, bt_hi.y);
            float n1z = fmaf((d4.z - mu) * rstd, g_hi.z, bt_hi.z);
            float n1w = fmaf((d4.w - mu) * rstd, g_hi.w, bt_hi.w);

            uint32_t h0, l0, h1, l1, h2, l2, h3, l3;
            split2h(n0x, n0y, h0, l0);
            split2h(n0z, n0w, h1, l1);
            split2h(n1x, n1y, h2, l2);
            split2h(n1z, n1w, h3, l3);

            const int row = warp * EPW + e;
            char* Ah = smem + OFF_AH + row * RSTRIDE;
            char* Al = smem + OFF_AL + row * RSTRIDE;
            *reinterpret_cast<uint64_t*>(Ah + lane * 8)       = (uint64_t)h0 | ((uint64_t)h1 << 32);
            *reinterpret_cast<uint64_t*>(Ah + 256 + lane * 8) = (uint64_t)h2 | ((uint64_t)h3 << 32);
            *reinterpret_cast<uint64_t*>(Al + lane * 8)       = (uint64_t)l0 | ((uint64_t)l1 << 32);
            *reinterpret_cast<uint64_t*>(Al + 256 + lane * 8) = (uint64_t)l2 | ((uint64_t)l3 << 32);
        }
        __syncthreads();

        // ---- Prefetch next tile's gathers; completes under the GEMM below ----
        if (tn < ntiles)
            load_tile(tn * M_TILE + warp * EPW, E, lane, src, dst, a, x, vs, vd, av);

        // ================= Phase B: 2-term fp16 HMMA GEMM =================
        float d[8][4];
        #pragma unroll
        for (int n = 0; n < 8; n++) { d[n][0] = d[n][1] = d[n][2] = d[n][3] = 0.0f; }

        #pragma unroll 2
        for (int kk = 0; kk < 16; kk++) {
            uint32_t ah0, ah1, ah2, ah3, al0, al1, al2, al3;
            ldmatrix_x4(ah0, ah1, ah2, ah3, a_hi_addr + kk * 32);
            ldmatrix_x4(al0, al1, al2, al3, a_lo_addr + kk * 32);
            #pragma unroll
            for (int pr = 0; pr < 4; pr++) {
                uint32_t b0, b1, b2r, b3;
                ldmatrix_x4(b0, b1, b2r, b3, b_addr + pr * 16 * RSTRIDE + kk * 32);
                mma_f16(d[2 * pr],     ah0, ah1, ah2, ah3, b0, b1);
                mma_f16(d[2 * pr + 1], ah0, ah1, ah2, ah3, b2r, b3);
                mma_f16(d[2 * pr],     al0, al1, al2, al3, b0, b1);
                mma_f16(d[2 * pr + 1], al0, al1, al2, al3, b2r, b3);
            }
        }

        // ================= Epilogue: bias + ELU + dot(W2) =================
        float p0 = 0.0f, p1 = 0.0f;
        #pragma unroll
        for (int n = 0; n < 8; n++) {
            const int j0 = jbase + n * 8 + (lane & 3) * 2;
            const float bb0 = sb1[j0],     bb1 = sb1[j0 + 1];
            const float ww0 = sw2[j0],     ww1 = sw2[j0 + 1];
            float v;
            v = d[n][0] + bb0; v = v > 0.0f ? v : (__expf(v) - 1.0f); p0 = fmaf(v, ww0, p0);
            v = d[n][1] + bb1; v = v > 0.0f ? v : (__expf(v) - 1.0f); p0 = fmaf(v, ww1, p0);
            v = d[n][2] + bb0; v = v > 0.0f ? v : (__expf(v) - 1.0f); p1 = fmaf(v, ww0, p1);
            v = d[n][3] + bb1; v = v > 0.0f ? v : (__expf(v) - 1.0f); p1 = fmaf(v, ww1, p1);
        }
        p0 += __shfl_xor_sync(0xffffffffu, p0, 1);
        p0 += __shfl_xor_sync(0xffffffffu, p0, 2);
        p1 += __shfl_xor_sync(0xffffffffu, p1, 1);
        p1 += __shfl_xor_sync(0xffffffffu, p1, 2);

        const int r0 = mbase + (lane >> 2);
        const int r1 = r0 + 8;
        if ((warp & 1) == 1 && (lane & 3) == 0) {
            pbuf[r0] = p0;
            pbuf[r1] = p1;
        }
        __syncthreads();
        if ((warp & 1) == 0 && (lane & 3) == 0) {
            const int e0 = ebase + r0;
            const int e1 = ebase + r1;
            if (e0 < E) out[e0] = p0 + pbuf[r0] + b2v;
            if (e1 < E) out[e1] = p1 + pbuf[r1] + b2v;
        }
        t = tn;
    }
}

extern "C" void kernel_launch(void* const* d_in, const int* in_sizes, int n_in,
                              void* d_out, int out_size)
{
    const float* x     = (const float*)d_in[0];
    const int*   src   = (const int*)  d_in[1];
    const int*   dst   = (const int*)  d_in[2];
    const float* a     = (const float*)d_in[3];
    const float* W1    = (const float*)d_in[4];
    const float* b1    = (const float*)d_in[5];
    const float* W2    = (const float*)d_in[6];
    const float* b2    = (const float*)d_in[7];
    const float* gamma = (const float*)d_in[8];
    const float* beta  = (const float*)d_in[9];
    float* out = (float*)d_out;
    const int E = in_sizes[1];

    cudaFuncSetAttribute(edge_mlp_hmma_kernel,
                         cudaFuncAttributeMaxDynamicSharedMemorySize, SMEM_TOTAL);
    edge_mlp_hmma_kernel<<<148, TPB, SMEM_TOTAL>>>(x, src, dst, a, W1, b1, W2, b2,
                                                   gamma, beta, out, E);
}

// round 7
// speedup vs baseline: 3.4563x; 1.1644x over previous
#include <cuda_runtime.h>
#include <cuda_fp16.h>
#include <cstdint>

#define DEV __device__ __forceinline__

DEV uint32_t smem_u32(const void* p) {
    uint32_t a;
    asm("{ .reg .u64 t; cvta.to.shared.u64 t, %1; cvt.u32.u64 %0, t; }" : "=r"(a) : "l"(p));
    return a;
}

DEV void ldmatrix_x4(uint32_t& r0, uint32_t& r1, uint32_t& r2, uint32_t& r3, uint32_t addr) {
    asm volatile("ldmatrix.sync.aligned.m8n8.x4.shared.b16 {%0,%1,%2,%3}, [%4];"
                 : "=r"(r0), "=r"(r1), "=r"(r2), "=r"(r3) : "r"(addr));
}

DEV void mma_f16(float* d, uint32_t a0, uint32_t a1, uint32_t a2, uint32_t a3,
                 uint32_t b0, uint32_t b1) {
    asm volatile("mma.sync.aligned.m16n8k16.row.col.f32.f16.f16.f32 "
                 "{%0,%1,%2,%3}, {%4,%5,%6,%7}, {%8,%9}, {%0,%1,%2,%3};"
                 : "+f"(d[0]), "+f"(d[1]), "+f"(d[2]), "+f"(d[3])
                 : "r"(a0), "r"(a1), "r"(a2), "r"(a3), "r"(b0), "r"(b1));
}

DEV void split2h(float a, float b, uint32_t& hi, uint32_t& lo) {
    __half ah = __float2half_rn(a);
    __half bh = __float2half_rn(b);
    float ar = a - __half2float(ah);
    float br = b - __half2float(bh);
    __half al = __float2half_rn(ar);
    __half bl = __float2half_rn(br);
    hi = (uint32_t)__half_as_ushort(ah) | ((uint32_t)__half_as_ushort(bh) << 16);
    lo = (uint32_t)__half_as_ushort(al) | ((uint32_t)__half_as_ushort(bl) << 16);
}

#define BAR_SYNC(id, cnt)   asm volatile("bar.sync %0, %1;"   :: "r"(id), "r"(cnt) : "memory")
#define BAR_ARRIVE(id, cnt) asm volatile("bar.arrive %0, %1;" :: "r"(id), "r"(cnt) : "memory")
#define MEMBAR_CTA()        asm volatile("membar.cta;" ::: "memory")

constexpr int TPB    = 384;     // 12 warps: 4 producers + 8 consumers
constexpr int M_TILE = 64;
constexpr float LN_EPS = 1e-5f;

constexpr int RSTRIDE = 528;                     // 256 fp16 + 8 pad
constexpr int ABUF_HALF = 64 * RSTRIDE;          // 33792 (hi or lo block)
constexpr int ABUF = 2 * ABUF_HALF;              // 67584 per buffer

// SMEM layout (bytes)
constexpr int OFF_W    = 0;                      // W1^T fp16: 128 x 528 = 67584
constexpr int OFF_A    = OFF_W + 128 * RSTRIDE;  // A dbl-buf: 2 x 67584 = 135168
constexpr int OFF_PB   = OFF_A + 2 * ABUF;       // pbuf: 2 x 64 f = 512
constexpr int OFF_SB1  = OFF_PB + 512;           // b1 128 f
constexpr int OFF_SW2  = OFF_SB1 + 512;          // W2 128 f
constexpr int OFF_G    = OFF_SW2 + 512;          // gamma 256 f
constexpr int OFF_BETA = OFF_G + 1024;           // beta 256 f
constexpr int SMEM_TOTAL = OFF_BETA + 1024;      // 206336

// barrier ids
constexpr int BAR_FULL0  = 1;   // producers arrive (128), consumers sync (256) -> 384
constexpr int BAR_EMPTY0 = 3;   // consumers arrive (256), producers sync (128) -> 384
constexpr int BAR_CONS   = 5;   // consumer-internal, 256

DEV void loadQ(int base_ei, int E, int lane,
               const int* __restrict__ src, const int* __restrict__ dst,
               const float* __restrict__ a, const float* __restrict__ x,
               float4* vs, float4* vd, float* av)
{
    #pragma unroll
    for (int e = 0; e < 4; e++) {
        int ei = min(base_ei + e, E - 1);
        int si = __ldg(src + ei);
        int di = __ldg(dst + ei);
        av[e]  = __ldg(a + ei);
        vs[e]  = __ldg(reinterpret_cast<const float4*>(x + (size_t)si * 128) + lane);
        vd[e]  = __ldg(reinterpret_cast<const float4*>(x + (size_t)di * 128) + lane);
    }
}

__global__ __launch_bounds__(TPB, 1)
void edge_mlp_ws_kernel(const float* __restrict__ x,
                        const int*   __restrict__ src,
                        const int*   __restrict__ dst,
                        const float* __restrict__ a,
                        const float* __restrict__ W1,
                        const float* __restrict__ b1,
                        const float* __restrict__ W2,
                        const float* __restrict__ b2,
                        const float* __restrict__ gamma,
                        const float* __restrict__ beta,
                        float* __restrict__ out,
                        int E)
{
    extern __shared__ char smem[];
    float* pbuf = reinterpret_cast<float*>(smem + OFF_PB);
    float* sb1  = reinterpret_cast<float*>(smem + OFF_SB1);
    float* sw2  = reinterpret_cast<float*>(smem + OFF_SW2);
    float* sg   = reinterpret_cast<float*>(smem + OFF_G);
    float* sbt  = reinterpret_cast<float*>(smem + OFF_BETA);

    const int tid  = threadIdx.x;
    const int warp = tid >> 5;
    const int lane = tid & 31;
    const uint32_t sbase = smem_u32(smem);

    // ---- Stage W1^T (fp16) + params
    for (int idx = tid; idx < 256 * 128; idx += TPB) {
        int k = idx >> 7, j = idx & 127;
        *reinterpret_cast<__half*>(smem + OFF_W + j * RSTRIDE + k * 2) =
            __float2half_rn(__ldg(W1 + idx));
    }
    for (int i = tid; i < 256; i += TPB) { sg[i] = __ldg(gamma + i); sbt[i] = __ldg(beta + i); }
    if (tid < 128) { sb1[tid] = __ldg(b1 + tid); sw2[tid] = __ldg(W2 + tid); }
    __syncthreads();

    const int ntiles = (E + M_TILE - 1) / M_TILE;

    if (warp < 4) {
        // ======================= PRODUCER (4 warps, 1/SMSP) =======================
        const int pw = warp;
        const int g0 = lane * 4;
        const float4 g_lo  = *reinterpret_cast<const float4*>(sg  + g0);
        const float4 g_hi  = *reinterpret_cast<const float4*>(sg  + 128 + g0);
        const float4 bt_lo = *reinterpret_cast<const float4*>(sbt + g0);
        const float4 bt_hi = *reinterpret_cast<const float4*>(sbt + 128 + g0);

        float4 vs[2][4], vd[2][4];
        float  av[2][4];

        int t = blockIdx.x;
        if (t < ntiles)
            loadQ(t * M_TILE + pw * 16, E, lane, src, dst, a, x, vs[0], vd[0], av[0]);

        int it = 0;
        while (t < ntiles) {
            const int b = it & 1;
            BAR_SYNC(BAR_EMPTY0 + b, 384);

            char* Abh = smem + OFF_A + b * ABUF;            // hi block
            char* Abl = Abh + ABUF_HALF;                    // lo block
            const int tn = t + gridDim.x;

            #pragma unroll
            for (int q = 0; q < 4; q++) {
                const int cur = q & 1, nxt = cur ^ 1;
                // prefetch next quarter (or next tile's first quarter)
                if (q < 3) {
                    loadQ(t * M_TILE + pw * 16 + (q + 1) * 4, E, lane, src, dst, a, x,
                          vs[nxt], vd[nxt], av[nxt]);
                } else {
                    const int tt = (tn < ntiles) ? tn : t;
                    loadQ(tt * M_TILE + pw * 16, E, lane, src, dst, a, x,
                          vs[nxt], vd[nxt], av[nxt]);
                }
                // process current quarter
                #pragma unroll
                for (int e = 0; e < 4; e++) {
                    const float ae = av[cur][e];
                    float4 s4 = vs[cur][e], d4 = vd[cur][e];
                    s4.x *= ae; s4.y *= ae; s4.z *= ae; s4.w *= ae;
                    d4.x *= ae; d4.y *= ae; d4.z *= ae; d4.w *= ae;

                    float sum = (s4.x + s4.y) + (s4.z + s4.w) + (d4.x + d4.y) + (d4.z + d4.w);
                    float sq = s4.x * s4.x;
                    sq = fmaf(s4.y, s4.y, sq); sq = fmaf(s4.z, s4.z, sq); sq = fmaf(s4.w, s4.w, sq);
                    sq = fmaf(d4.x, d4.x, sq); sq = fmaf(d4.y, d4.y, sq);
                    sq = fmaf(d4.z, d4.z, sq); sq = fmaf(d4.w, d4.w, sq);
                    #pragma unroll
                    for (int o = 16; o > 0; o >>= 1) {
                        sum += __shfl_xor_sync(0xffffffffu, sum, o);
                        sq  += __shfl_xor_sync(0xffffffffu, sq,  o);
                    }
                    const float mu   = sum * (1.0f / 256.0f);
                    const float var  = fmaf(-mu, mu, sq * (1.0f / 256.0f));
                    const float rstd = rsqrtf(var + LN_EPS);

                    float n0x = fmaf((s4.x - mu) * rstd, g_lo.x, bt_lo.x);
                    float n0y = fmaf((s4.y - mu) * rstd, g_lo.y, bt_lo.y);
                    float n0z = fmaf((s4.z - mu) * rstd, g_lo.z, bt_lo.z);
                    float n0w = fmaf((s4.w - mu) * rstd, g_lo.w, bt_lo.w);
                    float n1x = fmaf((d4.x - mu) * rstd, g_hi.x, bt_hi.x);
                    float n1y = fmaf((d4.y - mu) * rstd, g_hi.y, bt_hi.y);
                    float n1z = fmaf((d4.z - mu) * rstd, g_hi.z, bt_hi.z);
                    float n1w = fmaf((d4.w - mu) * rstd, g_hi.w, bt_hi.w);

                    uint32_t h0, l0, h1, l1, h2, l2, h3, l3;
                    split2h(n0x, n0y, h0, l0);
                    split2h(n0z, n0w, h1, l1);
                    split2h(n1x, n1y, h2, l2);
                    split2h(n1z, n1w, h3, l3);

                    const int row = pw * 16 + q * 4 + e;
                    char* Ah = Abh + row * RSTRIDE;
                    char* Al = Abl + row * RSTRIDE;
                    *reinterpret_cast<uint64_t*>(Ah + lane * 8)       = (uint64_t)h0 | ((uint64_t)h1 << 32);
                    *reinterpret_cast<uint64_t*>(Ah + 256 + lane * 8) = (uint64_t)h2 | ((uint64_t)h3 << 32);
                    *reinterpret_cast<uint64_t*>(Al + lane * 8)       = (uint64_t)l0 | ((uint64_t)l1 << 32);
                    *reinterpret_cast<uint64_t*>(Al + 256 + lane * 8) = (uint64_t)l2 | ((uint64_t)l3 << 32);
                }
            }
            MEMBAR_CTA();
            BAR_ARRIVE(BAR_FULL0 + b, 384);
            t = tn;
            it++;
        }
    } else {
        // ======================= CONSUMER (8 warps, 2/SMSP) =======================
        const int cw = warp - 4;
        const int mbase = (cw >> 1) * 16;
        const int jbase = (cw & 1) * 64;

        const int arow  = (lane & 7) + ((lane >> 3) & 1) * 8;
        const int acolb = ((lane >> 4) & 1) * 16;
        const int brow  = (lane & 7) + ((lane >> 4) & 1) * 8;
        const int bkb   = ((lane >> 3) & 1) * 16;

        const uint32_t b_addr = sbase + OFF_W + (jbase + brow) * RSTRIDE + bkb;
        uint32_t a_hi[2], a_lo[2];
        #pragma unroll
        for (int b = 0; b < 2; b++) {
            a_hi[b] = sbase + OFF_A + b * ABUF + (mbase + arow) * RSTRIDE + acolb;
            a_lo[b] = a_hi[b] + ABUF_HALF;
        }
        const float b2v = __ldg(b2);

        // initial: both buffers are empty
        BAR_ARRIVE(BAR_EMPTY0 + 0, 384);
        BAR_ARRIVE(BAR_EMPTY0 + 1, 384);

        int t = blockIdx.x;
        int it = 0;
        while (t < ntiles) {
            const int b = it & 1;
            BAR_SYNC(BAR_FULL0 + b, 384);

            float d[8][4];
            #pragma unroll
            for (int n = 0; n < 8; n++) { d[n][0] = d[n][1] = d[n][2] = d[n][3] = 0.0f; }

            #pragma unroll 2
            for (int kk = 0; kk < 16; kk++) {
                uint32_t ah0, ah1, ah2, ah3, al0, al1, al2, al3;
                ldmatrix_x4(ah0, ah1, ah2, ah3, a_hi[b] + kk * 32);
                ldmatrix_x4(al0, al1, al2, al3, a_lo[b] + kk * 32);
                uint32_t bf[4][4];
                #pragma unroll
                for (int pr = 0; pr < 4; pr++)
                    ldmatrix_x4(bf[pr][0], bf[pr][1], bf[pr][2], bf[pr][3],
                                b_addr + pr * 16 * RSTRIDE + kk * 32);
                #pragma unroll
                for (int pr = 0; pr < 4; pr++) {
                    mma_f16(d[2 * pr],     ah0, ah1, ah2, ah3, bf[pr][0], bf[pr][1]);
                    mma_f16(d[2 * pr + 1], ah0, ah1, ah2, ah3, bf[pr][2], bf[pr][3]);
                }
                #pragma unroll
                for (int pr = 0; pr < 4; pr++) {
                    mma_f16(d[2 * pr],     al0, al1, al2, al3, bf[pr][0], bf[pr][1]);
                    mma_f16(d[2 * pr + 1], al0, al1, al2, al3, bf[pr][2], bf[pr][3]);
                }
            }

            // ---- epilogue compute (consumes all d -> LDSM of buf b complete) ----
            float p0 = 0.0f, p1 = 0.0f;
            #pragma unroll
            for (int n = 0; n < 8; n++) {
                const int j0 = jbase + n * 8 + (lane & 3) * 2;
                const float bb0 = sb1[j0],     bb1 = sb1[j0 + 1];
                const float ww0 = sw2[j0],     ww1 = sw2[j0 + 1];
                float v;
                v = d[n][0] + bb0; v = v > 0.0f ? v : (__expf(v) - 1.0f); p0 = fmaf(v, ww0, p0);
                v = d[n][1] + bb1; v = v > 0.0f ? v : (__expf(v) - 1.0f); p0 = fmaf(v, ww1, p0);
                v = d[n][2] + bb0; v = v > 0.0f ? v : (__expf(v) - 1.0f); p1 = fmaf(v, ww0, p1);
                v = d[n][3] + bb1; v = v > 0.0f ? v : (__expf(v) - 1.0f); p1 = fmaf(v, ww1, p1);
            }
            p0 += __shfl_xor_sync(0xffffffffu, p0, 1);
            p0 += __shfl_xor_sync(0xffffffffu, p0, 2);
            p1 += __shfl_xor_sync(0xffffffffu, p1, 1);
            p1 += __shfl_xor_sync(0xffffffffu, p1, 2);

            // A-buffer free for producers
            BAR_ARRIVE(BAR_EMPTY0 + b, 384);

            const int r0 = mbase + (lane >> 2);
            const int r1 = r0 + 8;
            if ((cw & 1) == 1 && (lane & 3) == 0) {
                pbuf[b * 64 + r0] = p0;
                pbuf[b * 64 + r1] = p1;
            }
            BAR_SYNC(BAR_CONS, 256);
            if ((cw & 1) == 0 && (lane & 3) == 0) {
                const int ebase = t * M_TILE;
                const int e0 = ebase + r0;
                const int e1 = ebase + r1;
                if (e0 < E) out[e0] = p0 + pbuf[b * 64 + r0] + b2v;
                if (e1 < E) out[e1] = p1 + pbuf[b * 64 + r1] + b2v;
            }
            t += gridDim.x;
            it++;
        }
    }
}

extern "C" void kernel_launch(void* const* d_in, const int* in_sizes, int n_in,
                              void* d_out, int out_size)
{
    const float* x     = (const float*)d_in[0];
    const int*   src   = (const int*)  d_in[1];
    const int*   dst   = (const int*)  d_in[2];
    const float* a     = (const float*)d_in[3];
    const float* W1    = (const float*)d_in[4];
    const float* b1    = (const float*)d_in[5];
    const float* W2    = (const float*)d_in[6];
    const float* b2    = (const float*)d_in[7];
    const float* gamma = (const float*)d_in[8];
    const float* beta  = (const float*)d_in[9];
    float* out = (float*)d_out;
    const int E = in_sizes[1];

    cudaFuncSetAttribute(edge_mlp_ws_kernel,
                         cudaFuncAttributeMaxDynamicSharedMemorySize, SMEM_TOTAL);
    edge_mlp_ws_kernel<<<148, TPB, SMEM_TOTAL>>>(x, src, dst, a, W1, b1, W2, b2,
                                                 gamma, beta, out, E);
}

// round 8
// speedup vs baseline: 3.5967x; 1.0406x over previous
#include <cuda_runtime.h>
#include <cuda_fp16.h>
#include <cstdint>
#include <cstring>

#define DEV __device__ __forceinline__

DEV uint32_t smem_u32(const void* p) {
    uint32_t a;
    asm("{ .reg .u64 t; cvta.to.shared.u64 t, %1; cvt.u32.u64 %0, t; }" : "=r"(a) : "l"(p));
    return a;
}

DEV void ldmatrix_x4(uint32_t& r0, uint32_t& r1, uint32_t& r2, uint32_t& r3, uint32_t addr) {
    asm volatile("ldmatrix.sync.aligned.m8n8.x4.shared.b16 {%0,%1,%2,%3}, [%4];"
                 : "=r"(r0), "=r"(r1), "=r"(r2), "=r"(r3) : "r"(addr));
}

DEV void mma_f16(float* d, uint32_t a0, uint32_t a1, uint32_t a2, uint32_t a3,
                 uint32_t b0, uint32_t b1) {
    asm volatile("mma.sync.aligned.m16n8k16.row.col.f32.f16.f16.f32 "
                 "{%0,%1,%2,%3}, {%4,%5,%6,%7}, {%8,%9}, {%0,%1,%2,%3};"
                 : "+f"(d[0]), "+f"(d[1]), "+f"(d[2]), "+f"(d[3])
                 : "r"(a0), "r"(a1), "r"(a2), "r"(a3), "r"(b0), "r"(b1));
}

// fp16 hi/lo split of two floats via packed cvt (1 instr per pack)
DEV void split2h(float a, float b, uint32_t& hi, uint32_t& lo) {
    __half2 h2 = __float22half2_rn(make_float2(a, b));
    float2 hf = __half22float2(h2);
    __half2 l2 = __float22half2_rn(make_float2(a - hf.x, b - hf.y));
    memcpy(&hi, &h2, 4);
    memcpy(&lo, &l2, 4);
}

#define BAR_SYNC(id, cnt)   asm volatile("bar.sync %0, %1;"   :: "r"(id), "r"(cnt) : "memory")
#define BAR_ARRIVE(id, cnt) asm volatile("bar.arrive %0, %1;" :: "r"(id), "r"(cnt) : "memory")
#define MEMBAR_CTA()        asm volatile("membar.cta;" ::: "memory")

constexpr int TPB    = 512;     // 16 warps: 8 producers + 8 consumers
constexpr int M_TILE = 64;
constexpr float LN_EPS = 1e-5f;

constexpr int RSTRIDE = 528;                     // 256 fp16 + 8 pad
constexpr int ABUF_HALF = 64 * RSTRIDE;          // 33792 (hi or lo block)
constexpr int ABUF = 2 * ABUF_HALF;              // 67584 per buffer

// SMEM layout (bytes)
constexpr int OFF_W    = 0;                      // W1^T fp16: 128 x 528 = 67584
constexpr int OFF_A    = OFF_W + 128 * RSTRIDE;  // A dbl-buf: 2 x 67584 = 135168
constexpr int OFF_PB   = OFF_A + 2 * ABUF;       // pbuf: 2 x 64 f = 512
constexpr int OFF_SB1  = OFF_PB + 512;           // b1 128 f
constexpr int OFF_SW2  = OFF_SB1 + 512;          // W2 128 f
constexpr int OFF_G    = OFF_SW2 + 512;          // gamma 256 f
constexpr int OFF_BETA = OFF_G + 1024;           // beta 256 f
constexpr int SMEM_TOTAL = OFF_BETA + 1024;      // 206336

// barrier ids
constexpr int BAR_FULL0  = 1;   // producers arrive (256), consumers sync (256) -> 512
constexpr int BAR_EMPTY0 = 3;   // consumers arrive (256), producers sync (256) -> 512
constexpr int BAR_CONS   = 5;   // consumer-internal, 256

// load a PAIR of edges worth of gather data
DEV void loadP(int base_ei, int E, int lane,
               const int* __restrict__ src, const int* __restrict__ dst,
               const float* __restrict__ a, const float* __restrict__ x,
               float4* vs, float4* vd, float* av)
{
    #pragma unroll
    for (int e = 0; e < 2; e++) {
        int ei = min(base_ei + e, E - 1);
        int si = __ldg(src + ei);
        int di = __ldg(dst + ei);
        av[e]  = __ldg(a + ei);
        vs[e]  = __ldg(reinterpret_cast<const float4*>(x + (size_t)si * 128) + lane);
        vd[e]  = __ldg(reinterpret_cast<const float4*>(x + (size_t)di * 128) + lane);
    }
}

__global__ __launch_bounds__(TPB, 1)
void edge_mlp_ws_kernel(const float* __restrict__ x,
                        const int*   __restrict__ src,
                        const int*   __restrict__ dst,
                        const float* __restrict__ a,
                        const float* __restrict__ W1,
                        const float* __restrict__ b1,
                        const float* __restrict__ W2,
                        const float* __restrict__ b2,
                        const float* __restrict__ gamma,
                        const float* __restrict__ beta,
                        float* __restrict__ out,
                        int E)
{
    extern __shared__ char smem[];
    float* pbuf = reinterpret_cast<float*>(smem + OFF_PB);
    float* sb1  = reinterpret_cast<float*>(smem + OFF_SB1);
    float* sw2  = reinterpret_cast<float*>(smem + OFF_SW2);
    float* sg   = reinterpret_cast<float*>(smem + OFF_G);
    float* sbt  = reinterpret_cast<float*>(smem + OFF_BETA);

    const int tid  = threadIdx.x;
    const int warp = tid >> 5;
    const int lane = tid & 31;
    const uint32_t sbase = smem_u32(smem);

    // ---- Stage W1^T (fp16) + params
    for (int idx = tid; idx < 256 * 128; idx += TPB) {
        int k = idx >> 7, j = idx & 127;
        *reinterpret_cast<__half*>(smem + OFF_W + j * RSTRIDE + k * 2) =
            __float2half_rn(__ldg(W1 + idx));
    }
    for (int i = tid; i < 256; i += TPB) { sg[i] = __ldg(gamma + i); sbt[i] = __ldg(beta + i); }
    if (tid < 128) { sb1[tid] = __ldg(b1 + tid); sw2[tid] = __ldg(W2 + tid); }
    __syncthreads();

    const int ntiles = (E + M_TILE - 1) / M_TILE;

    if (warp < 8) {
        // ======================= PRODUCER (8 warps, 2/SMSP) =======================
        const int pw = warp;            // owns edges pw*8 .. pw*8+7 of each tile
        const int g0 = lane * 4;
        const float4 g_lo  = *reinterpret_cast<const float4*>(sg  + g0);
        const float4 g_hi  = *reinterpret_cast<const float4*>(sg  + 128 + g0);
        const float4 bt_lo = *reinterpret_cast<const float4*>(sbt + g0);
        const float4 bt_hi = *reinterpret_cast<const float4*>(sbt + 128 + g0);

        float4 vs[2][2], vd[2][2];
        float  av[2][2];

        int t = blockIdx.x;
        if (t < ntiles)
            loadP(t * M_TILE + pw * 8, E, lane, src, dst, a, x, vs[0], vd[0], av[0]);

        int it = 0;
        while (t < ntiles) {
            const int b = it & 1;
            BAR_SYNC(BAR_EMPTY0 + b, 512);

            char* Abh = smem + OFF_A + b * ABUF;
            char* Abl = Abh + ABUF_HALF;
            const int tn = t + gridDim.x;

            #pragma unroll
            for (int p = 0; p < 4; p++) {          // 4 pairs of edges
                const int cur = p & 1, nxt = cur ^ 1;
                if (p < 3) {
                    loadP(t * M_TILE + pw * 8 + (p + 1) * 2, E, lane, src, dst, a, x,
                          vs[nxt], vd[nxt], av[nxt]);
                } else {
                    const int tt = (tn < ntiles) ? tn : t;
                    loadP(tt * M_TILE + pw * 8, E, lane, src, dst, a, x,
                          vs[nxt], vd[nxt], av[nxt]);
                }
                #pragma unroll
                for (int e = 0; e < 2; e++) {
                    const float ae = av[cur][e];
                    float4 s4 = vs[cur][e], d4 = vd[cur][e];
                    s4.x *= ae; s4.y *= ae; s4.z *= ae; s4.w *= ae;
                    d4.x *= ae; d4.y *= ae; d4.z *= ae; d4.w *= ae;

                    float sum = (s4.x + s4.y) + (s4.z + s4.w) + (d4.x + d4.y) + (d4.z + d4.w);
                    float sq = s4.x * s4.x;
                    sq = fmaf(s4.y, s4.y, sq); sq = fmaf(s4.z, s4.z, sq); sq = fmaf(s4.w, s4.w, sq);
                    sq = fmaf(d4.x, d4.x, sq); sq = fmaf(d4.y, d4.y, sq);
                    sq = fmaf(d4.z, d4.z, sq); sq = fmaf(d4.w, d4.w, sq);
                    #pragma unroll
                    for (int o = 16; o > 0; o >>= 1) {
                        sum += __shfl_xor_sync(0xffffffffu, sum, o);
                        sq  += __shfl_xor_sync(0xffffffffu, sq,  o);
                    }
                    const float mu   = sum * (1.0f / 256.0f);
                    const float var  = fmaf(-mu, mu, sq * (1.0f / 256.0f));
                    const float rstd = rsqrtf(var + LN_EPS);

                    float n0x = fmaf((s4.x - mu) * rstd, g_lo.x, bt_lo.x);
                    float n0y = fmaf((s4.y - mu) * rstd, g_lo.y, bt_lo.y);
                    float n0z = fmaf((s4.z - mu) * rstd, g_lo.z, bt_lo.z);
                    float n0w = fmaf((s4.w - mu) * rstd, g_lo.w, bt_lo.w);
                    float n1x = fmaf((d4.x - mu) * rstd, g_hi.x, bt_hi.x);
                    float n1y = fmaf((d4.y - mu) * rstd, g_hi.y, bt_hi.y);
                    float n1z = fmaf((d4.z - mu) * rstd, g_hi.z, bt_hi.z);
                    float n1w = fmaf((d4.w - mu) * rstd, g_hi.w, bt_hi.w);

                    uint32_t h0, l0, h1, l1, h2, l2, h3, l3;
                    split2h(n0x, n0y, h0, l0);
                    split2h(n0z, n0w, h1, l1);
                    split2h(n1x, n1y, h2, l2);
                    split2h(n1z, n1w, h3, l3);

                    const int row = pw * 8 + p * 2 + e;
                    char* Ah = Abh + row * RSTRIDE;
                    char* Al = Abl + row * RSTRIDE;
                    *reinterpret_cast<uint64_t*>(Ah + lane * 8)       = (uint64_t)h0 | ((uint64_t)h1 << 32);
                    *reinterpret_cast<uint64_t*>(Ah + 256 + lane * 8) = (uint64_t)h2 | ((uint64_t)h3 << 32);
                    *reinterpret_cast<uint64_t*>(Al + lane * 8)       = (uint64_t)l0 | ((uint64_t)l1 << 32);
                    *reinterpret_cast<uint64_t*>(Al + 256 + lane * 8) = (uint64_t)l2 | ((uint64_t)l3 << 32);
                }
            }
            MEMBAR_CTA();
            BAR_ARRIVE(BAR_FULL0 + b, 512);
            t = tn;
            it++;
        }
    } else {
        // ======================= CONSUMER (8 warps, 2/SMSP) =======================
        const int cw = warp - 8;
        const int mbase = (cw >> 1) * 16;
        const int jbase = (cw & 1) * 64;

        const int arow  = (lane & 7) + ((lane >> 3) & 1) * 8;
        const int acolb = ((lane >> 4) & 1) * 16;
        const int brow  = (lane & 7) + ((lane >> 4) & 1) * 8;
        const int bkb   = ((lane >> 3) & 1) * 16;

        const uint32_t b_addr = sbase + OFF_W + (jbase + brow) * RSTRIDE + bkb;
        uint32_t a_hi[2], a_lo[2];
        #pragma unroll
        for (int b = 0; b < 2; b++) {
            a_hi[b] = sbase + OFF_A + b * ABUF + (mbase + arow) * RSTRIDE + acolb;
            a_lo[b] = a_hi[b] + ABUF_HALF;
        }
        const float b2v = __ldg(b2);

        BAR_ARRIVE(BAR_EMPTY0 + 0, 512);
        BAR_ARRIVE(BAR_EMPTY0 + 1, 512);

        int t = blockIdx.x;
        int it = 0;
        while (t < ntiles) {
            const int b = it & 1;
            BAR_SYNC(BAR_FULL0 + b, 512);

            float d[8][4];
            #pragma unroll
            for (int n = 0; n < 8; n++) { d[n][0] = d[n][1] = d[n][2] = d[n][3] = 0.0f; }

            #pragma unroll 2
            for (int kk = 0; kk < 16; kk++) {
                uint32_t ah0, ah1, ah2, ah3, al0, al1, al2, al3;
                ldmatrix_x4(ah0, ah1, ah2, ah3, a_hi[b] + kk * 32);
                ldmatrix_x4(al0, al1, al2, al3, a_lo[b] + kk * 32);
                uint32_t bf[4][4];
                #pragma unroll
                for (int pr = 0; pr < 4; pr++)
                    ldmatrix_x4(bf[pr][0], bf[pr][1], bf[pr][2], bf[pr][3],
                                b_addr + pr * 16 * RSTRIDE + kk * 32);
                #pragma unroll
                for (int pr = 0; pr < 4; pr++) {
                    mma_f16(d[2 * pr],     ah0, ah1, ah2, ah3, bf[pr][0], bf[pr][1]);
                    mma_f16(d[2 * pr + 1], ah0, ah1, ah2, ah3, bf[pr][2], bf[pr][3]);
                }
                #pragma unroll
                for (int pr = 0; pr < 4; pr++) {
                    mma_f16(d[2 * pr],     al0, al1, al2, al3, bf[pr][0], bf[pr][1]);
                    mma_f16(d[2 * pr + 1], al0, al1, al2, al3, bf[pr][2], bf[pr][3]);
                }
            }

            // ---- epilogue compute (consumes all d -> LDSM of buf b complete) ----
            float p0 = 0.0f, p1 = 0.0f;
            #pragma unroll
            for (int n = 0; n < 8; n++) {
                const int j0 = jbase + n * 8 + (lane & 3) * 2;
                const float bb0 = sb1[j0],     bb1 = sb1[j0 + 1];
                const float ww0 = sw2[j0],     ww1 = sw2[j0 + 1];
                float v;
                v = d[n][0] + bb0; v = v > 0.0f ? v : (__expf(v) - 1.0f); p0 = fmaf(v, ww0, p0);
                v = d[n][1] + bb1; v = v > 0.0f ? v : (__expf(v) - 1.0f); p0 = fmaf(v, ww1, p0);
                v = d[n][2] + bb0; v = v > 0.0f ? v : (__expf(v) - 1.0f); p1 = fmaf(v, ww0, p1);
                v = d[n][3] + bb1; v = v > 0.0f ? v : (__expf(v) - 1.0f); p1 = fmaf(v, ww1, p1);
            }
            p0 += __shfl_xor_sync(0xffffffffu, p0, 1);
            p0 += __shfl_xor_sync(0xffffffffu, p0, 2);
            p1 += __shfl_xor_sync(0xffffffffu, p1, 1);
            p1 += __shfl_xor_sync(0xffffffffu, p1, 2);

            BAR_ARRIVE(BAR_EMPTY0 + b, 512);

            const int r0 = mbase + (lane >> 2);
            const int r1 = r0 + 8;
            if ((cw & 1) == 1 && (lane & 3) == 0) {
                pbuf[b * 64 + r0] = p0;
                pbuf[b * 64 + r1] = p1;
            }
            BAR_SYNC(BAR_CONS, 256);
            if ((cw & 1) == 0 && (lane & 3) == 0) {
                const int ebase = t * M_TILE;
                const int e0 = ebase + r0;
                const int e1 = ebase + r1;
                if (e0 < E) out[e0] = p0 + pbuf[b * 64 + r0] + b2v;
                if (e1 < E) out[e1] = p1 + pbuf[b * 64 + r1] + b2v;
            }
            t += gridDim.x;
            it++;
        }
    }
}

extern "C" void kernel_launch(void* const* d_in, const int* in_sizes, int n_in,
                              void* d_out, int out_size)
{
    const float* x     = (const float*)d_in[0];
    const int*   src   = (const int*)  d_in[1];
    const int*   dst   = (const int*)  d_in[2];
    const float* a     = (const float*)d_in[3];
    const float* W1    = (const float*)d_in[4];
    const float* b1    = (const float*)d_in[5];
    const float* W2    = (const float*)d_in[6];
    const float* b2    = (const float*)d_in[7];
    const float* gamma = (const float*)d_in[8];
    const float* beta  = (const float*)d_in[9];
    float* out = (float*)d_out;
    const int E = in_sizes[1];

    cudaFuncSetAttribute(edge_mlp_ws_kernel,
                         cudaFuncAttributeMaxDynamicSharedMemorySize, SMEM_TOTAL);
    edge_mlp_ws_kernel<<<148, TPB, SMEM_TOTAL>>>(x, src, dst, a, W1, b1, W2, b2,
                                                 gamma, beta, out, E);
}

// round 9
// speedup vs baseline: 5.2023x; 1.4464x over previous
#include <cuda_runtime.h>
#include <cuda_fp16.h>
#include <cstdint>
#include <cstring>

#define DEV __device__ __forceinline__

DEV uint32_t smem_u32(const void* p) {
    uint32_t a;
    asm("{ .reg .u64 t; cvta.to.shared.u64 t, %1; cvt.u32.u64 %0, t; }" : "=r"(a) : "l"(p));
    return a;
}

DEV void ldmatrix_x4(uint32_t& r0, uint32_t& r1, uint32_t& r2, uint32_t& r3, uint32_t addr) {
    asm volatile("ldmatrix.sync.aligned.m8n8.x4.shared.b16 {%0,%1,%2,%3}, [%4];"
                 : "=r"(r0), "=r"(r1), "=r"(r2), "=r"(r3) : "r"(addr));
}

DEV void mma_f16(float* d, uint32_t a0, uint32_t a1, uint32_t a2, uint32_t a3,
                 uint32_t b0, uint32_t b1) {
    asm volatile("mma.sync.aligned.m16n8k16.row.col.f32.f16.f16.f32 "
                 "{%0,%1,%2,%3}, {%4,%5,%6,%7}, {%8,%9}, {%0,%1,%2,%3};"
                 : "+f"(d[0]), "+f"(d[1]), "+f"(d[2]), "+f"(d[3])
                 : "r"(a0), "r"(a1), "r"(a2), "r"(a3), "r"(b0), "r"(b1));
}

// pack two floats to fp16x2 (single packed cvt)
DEV uint32_t pack_h2(float a, float b) {
    __half2 h2 = __float22half2_rn(make_float2(a, b));
    uint32_t r;
    memcpy(&r, &h2, 4);
    return r;
}

#define BAR_SYNC(id, cnt)   asm volatile("bar.sync %0, %1;"   :: "r"(id), "r"(cnt) : "memory")
#define BAR_ARRIVE(id, cnt) asm volatile("bar.arrive %0, %1;" :: "r"(id), "r"(cnt) : "memory")
#define MEMBAR_CTA()        asm volatile("membar.cta;" ::: "memory")

constexpr int TPB    = 512;     // 16 warps: 8 producers + 8 consumers
constexpr int M_TILE = 128;
constexpr float LN_EPS = 1e-5f;

constexpr int RSTRIDE = 528;                     // 256 fp16 + 8 pad
constexpr int ABUF = 128 * RSTRIDE;              // 67584 per buffer (single fp16 block)

// SMEM layout (bytes)
constexpr int OFF_W    = 0;                      // W1^T fp16: 128 x 528 = 67584
constexpr int OFF_A    = OFF_W + 128 * RSTRIDE;  // A dbl-buf: 2 x 67584 = 135168
constexpr int OFF_PB   = OFF_A + 2 * ABUF;       // pbuf: 2 x 128 f = 1024
constexpr int OFF_SB1  = OFF_PB + 1024;          // b1 128 f
constexpr int OFF_SW2  = OFF_SB1 + 512;          // W2 128 f
constexpr int OFF_G    = OFF_SW2 + 512;          // gamma 256 f
constexpr int OFF_BETA = OFF_G + 1024;           // beta 256 f
constexpr int SMEM_TOTAL = OFF_BETA + 1024;      // 207872

// barrier ids
constexpr int BAR_FULL0  = 1;   // producers arrive (256), consumers sync (256) -> 512
constexpr int BAR_EMPTY0 = 3;   // consumers arrive (256), producers sync (256) -> 512
constexpr int BAR_CONS   = 5;   // consumer-internal, 256

// load a PAIR of edges worth of gather data
DEV void loadP(int base_ei, int E, int lane,
               const int* __restrict__ src, const int* __restrict__ dst,
               const float* __restrict__ a, const float* __restrict__ x,
               float4* vs, float4* vd, float* av)
{
    #pragma unroll
    for (int e = 0; e < 2; e++) {
        int ei = min(base_ei + e, E - 1);
        int si = __ldg(src + ei);
        int di = __ldg(dst + ei);
        av[e]  = __ldg(a + ei);
        vs[e]  = __ldg(reinterpret_cast<const float4*>(x + (size_t)si * 128) + lane);
        vd[e]  = __ldg(reinterpret_cast<const float4*>(x + (size_t)di * 128) + lane);
    }
}

__global__ __launch_bounds__(TPB, 1)
void edge_mlp_ws_kernel(const float* __restrict__ x,
                        const int*   __restrict__ src,
                        const int*   __restrict__ dst,
                        const float* __restrict__ a,
                        const float* __restrict__ W1,
                        const float* __restrict__ b1,
                        const float* __restrict__ W2,
                        const float* __restrict__ b2,
                        const float* __restrict__ gamma,
                        const float* __restrict__ beta,
                        float* __restrict__ out,
                        int E)
{
    extern __shared__ char smem[];
    float* pbuf = reinterpret_cast<float*>(smem + OFF_PB);
    float* sb1  = reinterpret_cast<float*>(smem + OFF_SB1);
    float* sw2  = reinterpret_cast<float*>(smem + OFF_SW2);
    float* sg   = reinterpret_cast<float*>(smem + OFF_G);
    float* sbt  = reinterpret_cast<float*>(smem + OFF_BETA);

    const int tid  = threadIdx.x;
    const int warp = tid >> 5;
    const int lane = tid & 31;
    const uint32_t sbase = smem_u32(smem);

    // ---- Stage W1^T (fp16) + params
    for (int idx = tid; idx < 256 * 128; idx += TPB) {
        int k = idx >> 7, j = idx & 127;
        *reinterpret_cast<__half*>(smem + OFF_W + j * RSTRIDE + k * 2) =
            __float2half_rn(__ldg(W1 + idx));
    }
    for (int i = tid; i < 256; i += TPB) { sg[i] = __ldg(gamma + i); sbt[i] = __ldg(beta + i); }
    if (tid < 128) { sb1[tid] = __ldg(b1 + tid); sw2[tid] = __ldg(W2 + tid); }
    __syncthreads();

    const int ntiles = (E + M_TILE - 1) / M_TILE;

    if (warp < 8) {
        // ======================= PRODUCER (8 warps, 2/SMSP) =======================
        const int pw = warp;            // owns rows pw*16 .. pw*16+15 of each tile
        const int g0 = lane * 4;
        const float4 g_lo  = *reinterpret_cast<const float4*>(sg  + g0);
        const float4 g_hi  = *reinterpret_cast<const float4*>(sg  + 128 + g0);
        const float4 bt_lo = *reinterpret_cast<const float4*>(sbt + g0);
        const float4 bt_hi = *reinterpret_cast<const float4*>(sbt + 128 + g0);

        float4 vs[2][2], vd[2][2];
        float  av[2][2];

        int t = blockIdx.x;
        if (t < ntiles)
            loadP(t * M_TILE + pw * 16, E, lane, src, dst, a, x, vs[0], vd[0], av[0]);

        int it = 0;
        while (t < ntiles) {
            const int b = it & 1;
            BAR_SYNC(BAR_EMPTY0 + b, 512);

            char* Ab = smem + OFF_A + b * ABUF;
            const int tn = t + gridDim.x;

            #pragma unroll
            for (int p = 0; p < 8; p++) {          // 8 pairs of edges
                const int cur = p & 1, nxt = cur ^ 1;
                if (p < 7) {
                    loadP(t * M_TILE + pw * 16 + (p + 1) * 2, E, lane, src, dst, a, x,
                          vs[nxt], vd[nxt], av[nxt]);
                } else {
                    const int tt = (tn < ntiles) ? tn : t;
                    loadP(tt * M_TILE + pw * 16, E, lane, src, dst, a, x,
                          vs[nxt], vd[nxt], av[nxt]);
                }
                #pragma unroll
                for (int e = 0; e < 2; e++) {
                    const float ae = av[cur][e];
                    float4 s4 = vs[cur][e], d4 = vd[cur][e];
                    s4.x *= ae; s4.y *= ae; s4.z *= ae; s4.w *= ae;
                    d4.x *= ae; d4.y *= ae; d4.z *= ae; d4.w *= ae;

                    float sum = (s4.x + s4.y) + (s4.z + s4.w) + (d4.x + d4.y) + (d4.z + d4.w);
                    float sq = s4.x * s4.x;
                    sq = fmaf(s4.y, s4.y, sq); sq = fmaf(s4.z, s4.z, sq); sq = fmaf(s4.w, s4.w, sq);
                    sq = fmaf(d4.x, d4.x, sq); sq = fmaf(d4.y, d4.y, sq);
                    sq = fmaf(d4.z, d4.z, sq); sq = fmaf(d4.w, d4.w, sq);
                    #pragma unroll
                    for (int o = 16; o > 0; o >>= 1) {
                        sum += __shfl_xor_sync(0xffffffffu, sum, o);
                        sq  += __shfl_xor_sync(0xffffffffu, sq,  o);
                    }
                    const float mu   = sum * (1.0f / 256.0f);
                    const float var  = fmaf(-mu, mu, sq * (1.0f / 256.0f));
                    const float rstd = rsqrtf(var + LN_EPS);

                    float n0x = fmaf((s4.x - mu) * rstd, g_lo.x, bt_lo.x);
                    float n0y = fmaf((s4.y - mu) * rstd, g_lo.y, bt_lo.y);
                    float n0z = fmaf((s4.z - mu) * rstd, g_lo.z, bt_lo.z);
                    float n0w = fmaf((s4.w - mu) * rstd, g_lo.w, bt_lo.w);
                    float n1x = fmaf((d4.x - mu) * rstd, g_hi.x, bt_hi.x);
                    float n1y = fmaf((d4.y - mu) * rstd, g_hi.y, bt_hi.y);
                    float n1z = fmaf((d4.z - mu) * rstd, g_hi.z, bt_hi.z);
                    float n1w = fmaf((d4.w - mu) * rstd, g_hi.w, bt_hi.w);

                    const uint32_t h0 = pack_h2(n0x, n0y);
                    const uint32_t h1 = pack_h2(n0z, n0w);
                    const uint32_t h2 = pack_h2(n1x, n1y);
                    const uint32_t h3 = pack_h2(n1z, n1w);

                    const int row = pw * 16 + p * 2 + e;
                    char* Ah = Ab + row * RSTRIDE;
                    *reinterpret_cast<uint64_t*>(Ah + lane * 8)       = (uint64_t)h0 | ((uint64_t)h1 << 32);
                    *reinterpret_cast<uint64_t*>(Ah + 256 + lane * 8) = (uint64_t)h2 | ((uint64_t)h3 << 32);
                }
            }
            MEMBAR_CTA();
            BAR_ARRIVE(BAR_FULL0 + b, 512);
            t = tn;
            it++;
        }
    } else {
        // ======================= CONSUMER (8 warps, 2/SMSP) =======================
        const int cw = warp - 8;
        const int mbase = (cw >> 1) * 32;      // 2 m16-subtiles per warp
        const int jbase = (cw & 1) * 64;

        const int arow  = (lane & 7) + ((lane >> 3) & 1) * 8;
        const int acolb = ((lane >> 4) & 1) * 16;
        const int brow  = (lane & 7) + ((lane >> 4) & 1) * 8;
        const int bkb   = ((lane >> 3) & 1) * 16;

        const uint32_t b_addr = sbase + OFF_W + (jbase + brow) * RSTRIDE + bkb;
        uint32_t a_addr[2][2];
        #pragma unroll
        for (int b = 0; b < 2; b++)
            #pragma unroll
            for (int mt = 0; mt < 2; mt++)
                a_addr[b][mt] = sbase + OFF_A + b * ABUF +
                                (mbase + mt * 16 + arow) * RSTRIDE + acolb;
        const float b2v = __ldg(b2);

        BAR_ARRIVE(BAR_EMPTY0 + 0, 512);
        BAR_ARRIVE(BAR_EMPTY0 + 1, 512);

        int t = blockIdx.x;
        int it = 0;
        while (t < ntiles) {
            const int b = it & 1;
            BAR_SYNC(BAR_FULL0 + b, 512);

            float d[2][8][4];
            #pragma unroll
            for (int mt = 0; mt < 2; mt++)
                #pragma unroll
                for (int n = 0; n < 8; n++)
                    d[mt][n][0] = d[mt][n][1] = d[mt][n][2] = d[mt][n][3] = 0.0f;

            #pragma unroll 2
            for (int kk = 0; kk < 16; kk++) {
                uint32_t a0[2], a1[2], a2[2], a3[2];
                #pragma unroll
                for (int mt = 0; mt < 2; mt++)
                    ldmatrix_x4(a0[mt], a1[mt], a2[mt], a3[mt], a_addr[b][mt] + kk * 32);
                uint32_t bf[4][4];
                #pragma unroll
                for (int pr = 0; pr < 4; pr++)
                    ldmatrix_x4(bf[pr][0], bf[pr][1], bf[pr][2], bf[pr][3],
                                b_addr + pr * 16 * RSTRIDE + kk * 32);
                #pragma unroll
                for (int mt = 0; mt < 2; mt++)
                    #pragma unroll
                    for (int pr = 0; pr < 4; pr++) {
                        mma_f16(d[mt][2 * pr],     a0[mt], a1[mt], a2[mt], a3[mt],
                                bf[pr][0], bf[pr][1]);
                        mma_f16(d[mt][2 * pr + 1], a0[mt], a1[mt], a2[mt], a3[mt],
                                bf[pr][2], bf[pr][3]);
                    }
            }

            // ---- epilogue: bias + ELU + dot(W2), per m-subtile ----
            float p[2][2];
            #pragma unroll
            for (int mt = 0; mt < 2; mt++) {
                float p0 = 0.0f, p1 = 0.0f;
                #pragma unroll
                for (int n = 0; n < 8; n++) {
                    const int j0 = jbase + n * 8 + (lane & 3) * 2;
                    const float bb0 = sb1[j0],     bb1 = sb1[j0 + 1];
                    const float ww0 = sw2[j0],     ww1 = sw2[j0 + 1];
                    float v;
                    v = d[mt][n][0] + bb0; v = v > 0.0f ? v : (__expf(v) - 1.0f); p0 = fmaf(v, ww0, p0);
                    v = d[mt][n][1] + bb1; v = v > 0.0f ? v : (__expf(v) - 1.0f); p0 = fmaf(v, ww1, p0);
                    v = d[mt][n][2] + bb0; v = v > 0.0f ? v : (__expf(v) - 1.0f); p1 = fmaf(v, ww0, p1);
                    v = d[mt][n][3] + bb1; v = v > 0.0f ? v : (__expf(v) - 1.0f); p1 = fmaf(v, ww1, p1);
                }
                p0 += __shfl_xor_sync(0xffffffffu, p0, 1);
                p0 += __shfl_xor_sync(0xffffffffu, p0, 2);
                p1 += __shfl_xor_sync(0xffffffffu, p1, 1);
                p1 += __shfl_xor_sync(0xffffffffu, p1, 2);
                p[mt][0] = p0;
                p[mt][1] = p1;
            }

            BAR_ARRIVE(BAR_EMPTY0 + b, 512);

            if ((cw & 1) == 1 && (lane & 3) == 0) {
                #pragma unroll
                for (int mt = 0; mt < 2; mt++) {
                    const int r0 = mbase + mt * 16 + (lane >> 2);
                    pbuf[b * 128 + r0]     = p[mt][0];
                    pbuf[b * 128 + r0 + 8] = p[mt][1];
                }
            }
            BAR_SYNC(BAR_CONS, 256);
            if ((cw & 1) == 0 && (lane & 3) == 0) {
                const int ebase = t * M_TILE;
                #pragma unroll
                for (int mt = 0; mt < 2; mt++) {
                    const int r0 = mbase + mt * 16 + (lane >> 2);
                    const int e0 = ebase + r0;
                    const int e1 = e0 + 8;
                    if (e0 < E) out[e0] = p[mt][0] + pbuf[b * 128 + r0] + b2v;
                    if (e1 < E) out[e1] = p[mt][1] + pbuf[b * 128 + r0 + 8] + b2v;
                }
            }
            t += gridDim.x;
            it++;
        }
    }
}

extern "C" void kernel_launch(void* const* d_in, const int* in_sizes, int n_in,
                              void* d_out, int out_size)
{
    const float* x     = (const float*)d_in[0];
    const int*   src   = (const int*)  d_in[1];
    const int*   dst   = (const int*)  d_in[2];
    const float* a     = (const float*)d_in[3];
    const float* W1    = (const float*)d_in[4];
    const float* b1    = (const float*)d_in[5];
    const float* W2    = (const float*)d_in[6];
    const float* b2    = (const float*)d_in[7];
    const float* gamma = (const float*)d_in[8];
    const float* beta  = (const float*)d_in[9];
    float* out = (float*)d_out;
    const int E = in_sizes[1];

    cudaFuncSetAttribute(edge_mlp_ws_kernel,
                         cudaFuncAttributeMaxDynamicSharedMemorySize, SMEM_TOTAL);
    edge_mlp_ws_kernel<<<148, TPB, SMEM_TOTAL>>>(x, src, dst, a, W1, b1, W2, b2,
                                                 gamma, beta, out, E);
}

// round 10
// speedup vs baseline: 5.3082x; 1.0204x over previous
#include <cuda_runtime.h>
#include <cuda_fp16.h>
#include <cstdint>
#include <cstring>

#define DEV __device__ __forceinline__

DEV uint32_t smem_u32(const void* p) {
    uint32_t a;
    asm("{ .reg .u64 t; cvta.to.shared.u64 t, %1; cvt.u32.u64 %0, t; }" : "=r"(a) : "l"(p));
    return a;
}

DEV void ldmatrix_x4(uint32_t& r0, uint32_t& r1, uint32_t& r2, uint32_t& r3, uint32_t addr) {
    asm volatile("ldmatrix.sync.aligned.m8n8.x4.shared.b16 {%0,%1,%2,%3}, [%4];"
                 : "=r"(r0), "=r"(r1), "=r"(r2), "=r"(r3) : "r"(addr));
}

DEV void mma_f16(float* d, uint32_t a0, uint32_t a1, uint32_t a2, uint32_t a3,
                 uint32_t b0, uint32_t b1) {
    asm volatile("mma.sync.aligned.m16n8k16.row.col.f32.f16.f16.f32 "
                 "{%0,%1,%2,%3}, {%4,%5,%6,%7}, {%8,%9}, {%0,%1,%2,%3};"
                 : "+f"(d[0]), "+f"(d[1]), "+f"(d[2]), "+f"(d[3])
                 : "r"(a0), "r"(a1), "r"(a2), "r"(a3), "r"(b0), "r"(b1));
}

DEV uint32_t pack_h2(float a, float b) {
    __half2 h2 = __float22half2_rn(make_float2(a, b));
    uint32_t r;
    memcpy(&r, &h2, 4);
    return r;
}

#define BAR_SYNC(id, cnt)   asm volatile("bar.sync %0, %1;"   :: "r"(id), "r"(cnt) : "memory")
#define BAR_ARRIVE(id, cnt) asm volatile("bar.arrive %0, %1;" :: "r"(id), "r"(cnt) : "memory")
#define MEMBAR_CTA()        asm volatile("membar.cta;" ::: "memory")

constexpr int TPB    = 512;     // 16 warps: 8 producers + 8 consumers
constexpr int M_TILE = 128;
constexpr float LN_EPS = 1e-5f;

constexpr int RSTRIDE = 528;                     // 256 fp16 + 8 pad
constexpr int ABUF = 128 * RSTRIDE;              // 67584 per buffer

// SMEM layout (bytes)
constexpr int OFF_W    = 0;                      // gamma*W1^T fp16: 128 x 528 = 67584
constexpr int OFF_A    = OFF_W + 128 * RSTRIDE;  // A dbl-buf: 2 x 67584 = 135168
constexpr int OFF_PB   = OFF_A + 2 * ABUF;       // pbuf: 2 x 128 f = 1024
constexpr int OFF_SC   = OFF_PB + 1024;          // sC: 128 float2 (c1, c2+b1) = 1024
constexpr int OFF_SS   = OFF_SC + 1024;          // sS: 2 x 128 float2 (s0,s1) = 2048
constexpr int OFF_SB1  = OFF_SS + 2048;          // b1 128 f
constexpr int OFF_SW2  = OFF_SB1 + 512;          // W2 128 f
constexpr int OFF_G    = OFF_SW2 + 512;          // gamma 256 f
constexpr int OFF_BETA = OFF_G + 1024;           // beta 256 f
constexpr int SMEM_TOTAL = OFF_BETA + 1024;      // 209920

constexpr int BAR_FULL0  = 1;
constexpr int BAR_EMPTY0 = 3;
constexpr int BAR_CONS   = 5;

DEV void loadP(int base_ei, int E, int lane,
               const int* __restrict__ src, const int* __restrict__ dst,
               const float* __restrict__ a, const float* __restrict__ x,
               float4* vs, float4* vd, float* av)
{
    #pragma unroll
    for (int e = 0; e < 2; e++) {
        int ei = min(base_ei + e, E - 1);
        int si = __ldg(src + ei);
        int di = __ldg(dst + ei);
        av[e]  = __ldg(a + ei);
        vs[e]  = __ldg(reinterpret_cast<const float4*>(x + (size_t)si * 128) + lane);
        vd[e]  = __ldg(reinterpret_cast<const float4*>(x + (size_t)di * 128) + lane);
    }
}

__global__ __launch_bounds__(TPB, 1)
void edge_mlp_ws_kernel(const float* __restrict__ x,
                        const int*   __restrict__ src,
                        const int*   __restrict__ dst,
                        const float* __restrict__ a,
                        const float* __restrict__ W1,
                        const float* __restrict__ b1,
                        const float* __restrict__ W2,
                        const float* __restrict__ b2,
                        const float* __restrict__ gamma,
                        const float* __restrict__ beta,
                        float* __restrict__ out,
                        int E)
{
    extern __shared__ char smem[];
    float*  pbuf = reinterpret_cast<float*>(smem + OFF_PB);
    float2* sC   = reinterpret_cast<float2*>(smem + OFF_SC);
    float2* sS   = reinterpret_cast<float2*>(smem + OFF_SS);
    float*  sb1  = reinterpret_cast<float*>(smem + OFF_SB1);
    float*  sw2  = reinterpret_cast<float*>(smem + OFF_SW2);
    float2* sw2v = reinterpret_cast<float2*>(smem + OFF_SW2);
    float*  sg   = reinterpret_cast<float*>(smem + OFF_G);
    float*  sbt  = reinterpret_cast<float*>(smem + OFF_BETA);

    const int tid  = threadIdx.x;
    const int warp = tid >> 5;
    const int lane = tid & 31;
    const uint32_t sbase = smem_u32(smem);

    // ---- params first (needed for W~ and c1/c2)
    for (int i = tid; i < 256; i += TPB) { sg[i] = __ldg(gamma + i); sbt[i] = __ldg(beta + i); }
    if (tid < 128) { sb1[tid] = __ldg(b1 + tid); sw2[tid] = __ldg(W2 + tid); }
    __syncthreads();

    // ---- Stage W~ = gamma_k * W1[k][j] (fp16), and c1/c2 columns
    for (int idx = tid; idx < 256 * 128; idx += TPB) {
        int k = idx >> 7, j = idx & 127;
        *reinterpret_cast<__half*>(smem + OFF_W + j * RSTRIDE + k * 2) =
            __float2half_rn(sg[k] * __ldg(W1 + idx));
    }
    if (tid < 128) {
        float c1 = 0.0f, c2 = 0.0f;
        for (int k = 0; k < 256; k++) {
            float w = __ldg(W1 + k * 128 + tid);
            c1 = fmaf(sg[k],  w, c1);
            c2 = fmaf(sbt[k], w, c2);
        }
        sC[tid] = make_float2(c1, c2 + sb1[tid]);
    }
    __syncthreads();

    const int ntiles = (E + M_TILE - 1) / M_TILE;

    if (warp < 8) {
        // ======================= PRODUCER (8 warps, 2/SMSP) =======================
        const int pw = warp;            // rows pw*16 .. pw*16+15 of each tile

        float4 vs[2][2], vd[2][2];
        float  av[2][2];

        int t = blockIdx.x;
        if (t < ntiles)
            loadP(t * M_TILE + pw * 16, E, lane, src, dst, a, x, vs[0], vd[0], av[0]);

        int it = 0;
        while (t < ntiles) {
            const int b = it & 1;
            BAR_SYNC(BAR_EMPTY0 + b, 512);

            char* Ab = smem + OFF_A + b * ABUF;
            const int tn = t + gridDim.x;

            #pragma unroll
            for (int p = 0; p < 8; p++) {          // 8 pairs of edges
                const int cur = p & 1, nxt = cur ^ 1;
                if (p < 7) {
                    loadP(t * M_TILE + pw * 16 + (p + 1) * 2, E, lane, src, dst, a, x,
                          vs[nxt], vd[nxt], av[nxt]);
                } else {
                    const int tt = (tn < ntiles) ? tn : t;
                    loadP(tt * M_TILE + pw * 16, E, lane, src, dst, a, x,
                          vs[nxt], vd[nxt], av[nxt]);
                }
                #pragma unroll
                for (int e = 0; e < 2; e++) {
                    const float4 s4 = vs[cur][e], d4 = vd[cur][e];
                    const int row = pw * 16 + p * 2 + e;
                    char* Ah = Ab + row * RSTRIDE;

                    // pack raw h to fp16 (independent of reduction — good ILP)
                    const uint32_t h0 = pack_h2(s4.x, s4.y);
                    const uint32_t h1 = pack_h2(s4.z, s4.w);
                    const uint32_t h2 = pack_h2(d4.x, d4.y);
                    const uint32_t h3 = pack_h2(d4.z, d4.w);
                    *reinterpret_cast<uint64_t*>(Ah + lane * 8)       = (uint64_t)h0 | ((uint64_t)h1 << 32);
                    *reinterpret_cast<uint64_t*>(Ah + 256 + lane * 8) = (uint64_t)h2 | ((uint64_t)h3 << 32);

                    // raw moments
                    float sum = (s4.x + s4.y) + (s4.z + s4.w) + (d4.x + d4.y) + (d4.z + d4.w);
                    float sq = s4.x * s4.x;
                    sq = fmaf(s4.y, s4.y, sq); sq = fmaf(s4.z, s4.z, sq); sq = fmaf(s4.w, s4.w, sq);
                    sq = fmaf(d4.x, d4.x, sq); sq = fmaf(d4.y, d4.y, sq);
                    sq = fmaf(d4.z, d4.z, sq); sq = fmaf(d4.w, d4.w, sq);
                    #pragma unroll
                    for (int o = 16; o > 0; o >>= 1) {
                        sum += __shfl_xor_sync(0xffffffffu, sum, o);
                        sq  += __shfl_xor_sync(0xffffffffu, sq,  o);
                    }
                    const float mu  = sum * (1.0f / 256.0f);
                    const float var = fmaf(-mu, mu, sq * (1.0f / 256.0f));
                    const float ae  = av[cur][e];
                    const float s1  = ae * rsqrtf(fmaf(ae * ae, var, LN_EPS));
                    const float s0  = -mu * s1;
                    if (lane == 0) sS[b * 128 + row] = make_float2(s0, s1);
                }
            }
            MEMBAR_CTA();
            BAR_ARRIVE(BAR_FULL0 + b, 512);
            t = tn;
            it++;
        }
    } else {
        // ======================= CONSUMER (8 warps, 2/SMSP) =======================
        const int cw = warp - 8;
        const int mbase = (cw >> 1) * 32;      // 2 m16-subtiles per warp
        const int jbase = (cw & 1) * 64;

        const int arow  = (lane & 7) + ((lane >> 3) & 1) * 8;
        const int acolb = ((lane >> 4) & 1) * 16;
        const int brow  = (lane & 7) + ((lane >> 4) & 1) * 8;
        const int bkb   = ((lane >> 3) & 1) * 16;

        const uint32_t b_addr = sbase + OFF_W + (jbase + brow) * RSTRIDE + bkb;
        uint32_t a_addr[2][2];
        #pragma unroll
        for (int b = 0; b < 2; b++)
            #pragma unroll
            for (int mt = 0; mt < 2; mt++)
                a_addr[b][mt] = sbase + OFF_A + b * ABUF +
                                (mbase + mt * 16 + arow) * RSTRIDE + acolb;
        const float b2v = __ldg(b2);

        BAR_ARRIVE(BAR_EMPTY0 + 0, 512);
        BAR_ARRIVE(BAR_EMPTY0 + 1, 512);

        int t = blockIdx.x;
        int it = 0;
        while (t < ntiles) {
            const int b = it & 1;
            BAR_SYNC(BAR_FULL0 + b, 512);

            float d[2][8][4];
            #pragma unroll
            for (int mt = 0; mt < 2; mt++)
                #pragma unroll
                for (int n = 0; n < 8; n++)
                    d[mt][n][0] = d[mt][n][1] = d[mt][n][2] = d[mt][n][3] = 0.0f;

            #pragma unroll 2
            for (int kk = 0; kk < 16; kk++) {
                uint32_t a0[2], a1[2], a2[2], a3[2];
                #pragma unroll
                for (int mt = 0; mt < 2; mt++)
                    ldmatrix_x4(a0[mt], a1[mt], a2[mt], a3[mt], a_addr[b][mt] + kk * 32);
                uint32_t bf[4][4];
                #pragma unroll
                for (int pr = 0; pr < 4; pr++)
                    ldmatrix_x4(bf[pr][0], bf[pr][1], bf[pr][2], bf[pr][3],
                                b_addr + pr * 16 * RSTRIDE + kk * 32);
                #pragma unroll
                for (int mt = 0; mt < 2; mt++)
                    #pragma unroll
                    for (int pr = 0; pr < 4; pr++) {
                        mma_f16(d[mt][2 * pr],     a0[mt], a1[mt], a2[mt], a3[mt],
                                bf[pr][0], bf[pr][1]);
                        mma_f16(d[mt][2 * pr + 1], a0[mt], a1[mt], a2[mt], a3[mt],
                                bf[pr][2], bf[pr][3]);
                    }
            }

            // ---- epilogue: z = s1*G + s0*c1 + (c2+b1), ELU, dot(W2) ----
            float p[2][2];
            #pragma unroll
            for (int mt = 0; mt < 2; mt++) {
                const int rA = mbase + mt * 16 + (lane >> 2);
                const float2 SA = sS[b * 128 + rA];
                const float2 SB = sS[b * 128 + rA + 8];
                float p0 = 0.0f, p1 = 0.0f;
                #pragma unroll
                for (int n = 0; n < 8; n++) {
                    const int j0 = jbase + n * 8 + (lane & 3) * 2;
                    const float2 C0 = sC[j0];
                    const float2 C1 = sC[j0 + 1];
                    const float2 W2p = sw2v[j0 >> 1];
                    float v;
                    v = fmaf(SA.y, d[mt][n][0], fmaf(SA.x, C0.x, C0.y));
                    v = v > 0.0f ? v : (__expf(v) - 1.0f); p0 = fmaf(v, W2p.x, p0);
                    v = fmaf(SA.y, d[mt][n][1], fmaf(SA.x, C1.x, C1.y));
                    v = v > 0.0f ? v : (__expf(v) - 1.0f); p0 = fmaf(v, W2p.y, p0);
                    v = fmaf(SB.y, d[mt][n][2], fmaf(SB.x, C0.x, C0.y));
                    v = v > 0.0f ? v : (__expf(v) - 1.0f); p1 = fmaf(v, W2p.x, p1);
                    v = fmaf(SB.y, d[mt][n][3], fmaf(SB.x, C1.x, C1.y));
                    v = v > 0.0f ? v : (__expf(v) - 1.0f); p1 = fmaf(v, W2p.y, p1);
                }
                p0 += __shfl_xor_sync(0xffffffffu, p0, 1);
                p0 += __shfl_xor_sync(0xffffffffu, p0, 2);
                p1 += __shfl_xor_sync(0xffffffffu, p1, 1);
                p1 += __shfl_xor_sync(0xffffffffu, p1, 2);
                p[mt][0] = p0;
                p[mt][1] = p1;
            }

            BAR_ARRIVE(BAR_EMPTY0 + b, 512);

            if ((cw & 1) == 1 && (lane & 3) == 0) {
                #pragma unroll
                for (int mt = 0; mt < 2; mt++) {
                    const int r0 = mbase + mt * 16 + (lane >> 2);
                    pbuf[b * 128 + r0]     = p[mt][0];
                    pbuf[b * 128 + r0 + 8] = p[mt][1];
                }
            }
            BAR_SYNC(BAR_CONS, 256);
            if ((cw & 1) == 0 && (lane & 3) == 0) {
                const int ebase = t * M_TILE;
                #pragma unroll
                for (int mt = 0; mt < 2; mt++) {
                    const int r0 = mbase + mt * 16 + (lane >> 2);
                    const int e0 = ebase + r0;
                    const int e1 = e0 + 8;
                    if (e0 < E) out[e0] = p[mt][0] + pbuf[b * 128 + r0] + b2v;
                    if (e1 < E) out[e1] = p[mt][1] + pbuf[b * 128 + r0 + 8] + b2v;
                }
            }
            t += gridDim.x;
            it++;
        }
    }
}

extern "C" void kernel_launch(void* const* d_in, const int* in_sizes, int n_in,
                              void* d_out, int out_size)
{
    const float* x     = (const float*)d_in[0];
    const int*   src   = (const int*)  d_in[1];
    const int*   dst   = (const int*)  d_in[2];
    const float* a     = (const float*)d_in[3];
    const float* W1    = (const float*)d_in[4];
    const float* b1    = (const float*)d_in[5];
    const float* W2    = (const float*)d_in[6];
    const float* b2    = (const float*)d_in[7];
    const float* gamma = (const float*)d_in[8];
    const float* beta  = (const float*)d_in[9];
    float* out = (float*)d_out;
    const int E = in_sizes[1];

    cudaFuncSetAttribute(edge_mlp_ws_kernel,
                         cudaFuncAttributeMaxDynamicSharedMemorySize, SMEM_TOTAL);
    edge_mlp_ws_kernel<<<148, TPB, SMEM_TOTAL>>>(x, src, dst, a, W1, b1, W2, b2,
                                                 gamma, beta, out, E);
}

// round 13
// speedup vs baseline: 5.7838x; 1.0896x over previous
#include <cuda_runtime.h>
#include <cuda_fp16.h>
#include <cstdint>
#include <cstring>

#define DEV __device__ __forceinline__

DEV uint32_t smem_u32(const void* p) {
    uint32_t a;
    asm("{ .reg .u64 t; cvta.to.shared.u64 t, %1; cvt.u32.u64 %0, t; }" : "=r"(a) : "l"(p));
    return a;
}

DEV void ldmatrix_x4(uint32_t& r0, uint32_t& r1, uint32_t& r2, uint32_t& r3, uint32_t addr) {
    asm volatile("ldmatrix.sync.aligned.m8n8.x4.shared.b16 {%0,%1,%2,%3}, [%4];"
                 : "=r"(r0), "=r"(r1), "=r"(r2), "=r"(r3) : "r"(addr));
}

DEV void mma_f16(float* d, uint32_t a0, uint32_t a1, uint32_t a2, uint32_t a3,
                 uint32_t b0, uint32_t b1) {
    asm volatile("mma.sync.aligned.m16n8k16.row.col.f32.f16.f16.f32 "
                 "{%0,%1,%2,%3}, {%4,%5,%6,%7}, {%8,%9}, {%0,%1,%2,%3};"
                 : "+f"(d[0]), "+f"(d[1]), "+f"(d[2]), "+f"(d[3])
                 : "r"(a0), "r"(a1), "r"(a2), "r"(a3), "r"(b0), "r"(b1));
}

DEV uint32_t pack_h2(float a, float b) {
    __half2 h2 = __float22half2_rn(make_float2(a, b));
    uint32_t r;
    memcpy(&r, &h2, 4);
    return r;
}

#define BAR_SYNC(id, cnt)   asm volatile("bar.sync %0, %1;"   :: "r"(id), "r"(cnt) : "memory")
#define BAR_ARRIVE(id, cnt) asm volatile("bar.arrive %0, %1;" :: "r"(id), "r"(cnt) : "memory")
#define MEMBAR_CTA()        asm volatile("membar.cta;" ::: "memory")

constexpr int TPB    = 512;     // 16 warps: 8 producers + 8 consumers
constexpr int M_TILE = 128;
constexpr float LN_EPS = 1e-5f;

constexpr int RSTRIDE = 528;                     // 256 fp16 + 8 pad
constexpr int ABUF = 128 * RSTRIDE;              // 67584 per buffer

// SMEM layout (bytes)
constexpr int OFF_W    = 0;                      // gamma*W1^T fp16: 128 x 528 = 67584
constexpr int OFF_A    = OFF_W + 128 * RSTRIDE;  // A dbl-buf: 2 x 67584 = 135168
constexpr int OFF_PB   = OFF_A + 2 * ABUF;       // pbuf: 2 x 128 f = 1024
constexpr int OFF_SC   = OFF_PB + 1024;          // sC: 128 float2 (c1, c2+b1) = 1024
constexpr int OFF_SS   = OFF_SC + 1024;          // sS: 4 x 128 float2 (s0,s1) = 4096
constexpr int OFF_SB1  = OFF_SS + 4096;          // b1 128 f
constexpr int OFF_SW2  = OFF_SB1 + 512;          // W2 128 f
constexpr int OFF_G    = OFF_SW2 + 512;          // gamma 256 f
constexpr int OFF_BETA = OFF_G + 1024;           // beta 256 f
constexpr int SMEM_TOTAL = OFF_BETA + 1024;      // 211968

constexpr int BAR_FULL0  = 1;
constexpr int BAR_EMPTY0 = 3;
constexpr int BAR_CONS   = 5;

// Load all 16 edges' metadata for this warp in one coalesced round.
// lanes 0-15: src idx; lanes 16-31: dst idx; all lanes: a value (dup x2).
DEV void loadMeta(int tbase, int E, int lane,
                  const int* __restrict__ src, const int* __restrict__ dst,
                  const float* __restrict__ a, int& ms, float& ma)
{
    int ei = min(tbase + (lane & 15), E - 1);
    ms = (lane < 16) ? __ldg(src + ei) : __ldg(dst + ei);
    ma = __ldg(a + ei);
}

// Issue gathers for edge pair e0,e0+1 using shfl'd metadata (no LDG dependency)
DEV void loadVec(int ms, int lane, const float* __restrict__ x, int e0,
                 float4* vs, float4* vd)
{
    int si0 = __shfl_sync(0xffffffffu, ms, e0);
    int di0 = __shfl_sync(0xffffffffu, ms, 16 + e0);
    int si1 = __shfl_sync(0xffffffffu, ms, e0 + 1);
    int di1 = __shfl_sync(0xffffffffu, ms, 17 + e0);
    vs[0] = __ldg(reinterpret_cast<const float4*>(x + (size_t)si0 * 128) + lane);
    vd[0] = __ldg(reinterpret_cast<const float4*>(x + (size_t)di0 * 128) + lane);
    vs[1] = __ldg(reinterpret_cast<const float4*>(x + (size_t)si1 * 128) + lane);
    vd[1] = __ldg(reinterpret_cast<const float4*>(x + (size_t)di1 * 128) + lane);
}

__global__ __launch_bounds__(TPB, 1)
void edge_mlp_ws_kernel(const float* __restrict__ x,
                        const int*   __restrict__ src,
                        const int*   __restrict__ dst,
                        const float* __restrict__ a,
                        const float* __restrict__ W1,
                        const float* __restrict__ b1,
                        const float* __restrict__ W2,
                        const float* __restrict__ b2,
                        const float* __restrict__ gamma,
                        const float* __restrict__ beta,
                        float* __restrict__ out,
                        int E)
{
    extern __shared__ char smem[];
    float*  pbuf = reinterpret_cast<float*>(smem + OFF_PB);
    float2* sC   = reinterpret_cast<float2*>(smem + OFF_SC);
    float2* sS   = reinterpret_cast<float2*>(smem + OFF_SS);
    float*  sb1  = reinterpret_cast<float*>(smem + OFF_SB1);
    float*  sw2  = reinterpret_cast<float*>(smem + OFF_SW2);
    float2* sw2v = reinterpret_cast<float2*>(smem + OFF_SW2);
    float*  sg   = reinterpret_cast<float*>(smem + OFF_G);
    float*  sbt  = reinterpret_cast<float*>(smem + OFF_BETA);

    const int tid  = threadIdx.x;
    const int warp = tid >> 5;
    const int lane = tid & 31;
    const uint32_t sbase = smem_u32(smem);

    // ---- params first (needed for W~ and c1/c2)
    for (int i = tid; i < 256; i += TPB) { sg[i] = __ldg(gamma + i); sbt[i] = __ldg(beta + i); }
    if (tid < 128) { sb1[tid] = __ldg(b1 + tid); sw2[tid] = __ldg(W2 + tid); }
    __syncthreads();

    // ---- Stage W~ = gamma_k * W1[k][j] (fp16), and c1/c2 columns
    for (int idx = tid; idx < 256 * 128; idx += TPB) {
        int k = idx >> 7, j = idx & 127;
        *reinterpret_cast<__half*>(smem + OFF_W + j * RSTRIDE + k * 2) =
            __float2half_rn(sg[k] * __ldg(W1 + idx));
    }
    if (tid < 128) {
        float c1 = 0.0f, c2 = 0.0f;
        for (int k = 0; k < 256; k++) {
            float w = __ldg(W1 + k * 128 + tid);
            c1 = fmaf(sg[k],  w, c1);
            c2 = fmaf(sbt[k], w, c2);
        }
        sC[tid] = make_float2(c1, c2 + sb1[tid]);
    }
    __syncthreads();

    const int ntiles = (E + M_TILE - 1) / M_TILE;

    if (warp < 8) {
        // ======================= PRODUCER (8 warps, 2/SMSP) =======================
        const int pw = warp;            // rows pw*16 .. pw*16+15 of each tile

        int   ms, msN;
        float ma, maN;
        float4 vs[2][2], vd[2][2];

        int t = blockIdx.x;
        if (t < ntiles) {
            loadMeta(t * M_TILE + pw * 16, E, lane, src, dst, a, ms, ma);
            loadVec(ms, lane, x, 0, vs[0], vd[0]);
        }

        int it = 0;
        while (t < ntiles) {
            const int b = it & 1;
            BAR_SYNC(BAR_EMPTY0 + b, 512);

            char* Ab = smem + OFF_A + b * ABUF;
            const int tn = t + gridDim.x;
            // next tile's metadata: issued now, consumed at p=7 (~2.5K cyc later)
            loadMeta((tn < ntiles ? tn : t) * M_TILE + pw * 16, E, lane,
                     src, dst, a, msN, maN);
            const int sslot = (it & 3) * 128;

            #pragma unroll
            for (int p = 0; p < 8; p++) {          // 8 pairs of edges
                const int cur = p & 1, nxt = cur ^ 1;
                if (p < 7) loadVec(ms,  lane, x, (p + 1) * 2, vs[nxt], vd[nxt]);
                else       loadVec(msN, lane, x, 0,           vs[nxt], vd[nxt]);

                #pragma unroll
                for (int e = 0; e < 2; e++) {
                    const float4 s4 = vs[cur][e], d4 = vd[cur][e];
                    const int row = pw * 16 + p * 2 + e;
                    char* Ah = Ab + row * RSTRIDE;

                    // pack raw h to fp16 (independent of reduction)
                    const uint32_t h0 = pack_h2(s4.x, s4.y);
                    const uint32_t h1 = pack_h2(s4.z, s4.w);
                    const uint32_t h2 = pack_h2(d4.x, d4.y);
                    const uint32_t h3 = pack_h2(d4.z, d4.w);
                    *reinterpret_cast<uint64_t*>(Ah + lane * 8)       = (uint64_t)h0 | ((uint64_t)h1 << 32);
                    *reinterpret_cast<uint64_t*>(Ah + 256 + lane * 8) = (uint64_t)h2 | ((uint64_t)h3 << 32);

                    // raw moments
                    float sum = (s4.x + s4.y) + (s4.z + s4.w) + (d4.x + d4.y) + (d4.z + d4.w);
                    float sq = s4.x * s4.x;
                    sq = fmaf(s4.y, s4.y, sq); sq = fmaf(s4.z, s4.z, sq); sq = fmaf(s4.w, s4.w, sq);
                    sq = fmaf(d4.x, d4.x, sq); sq = fmaf(d4.y, d4.y, sq);
                    sq = fmaf(d4.z, d4.z, sq); sq = fmaf(d4.w, d4.w, sq);
                    #pragma unroll
                    for (int o = 16; o > 0; o >>= 1) {
                        sum += __shfl_xor_sync(0xffffffffu, sum, o);
                        sq  += __shfl_xor_sync(0xffffffffu, sq,  o);
                    }
                    const float mu  = sum * (1.0f / 256.0f);
                    const float var = fmaf(-mu, mu, sq * (1.0f / 256.0f));
                    const float ae  = __shfl_sync(0xffffffffu, ma, p * 2 + e);
                    const float s1  = ae * rsqrtf(fmaf(ae * ae, var, LN_EPS));
                    const float s0  = -mu * s1;
                    if (lane == 0) sS[sslot + row] = make_float2(s0, s1);
                }
            }
            ms = msN; ma = maN;
            MEMBAR_CTA();
            BAR_ARRIVE(BAR_FULL0 + b, 512);
            t = tn;
            it++;
        }
    } else {
        // ======================= CONSUMER (8 warps, 2/SMSP) =======================
        const int cw = warp - 8;
        const int mbase = (cw >> 1) * 32;      // 2 m16-subtiles per warp
        const int jbase = (cw & 1) * 64;

        const int arow  = (lane & 7) + ((lane >> 3) & 1) * 8;
        const int acolb = ((lane >> 4) & 1) * 16;
        const int brow  = (lane & 7) + ((lane >> 4) & 1) * 8;
        const int bkb   = ((lane >> 3) & 1) * 16;

        const uint32_t b_addr = sbase + OFF_W + (jbase + brow) * RSTRIDE + bkb;
        uint32_t a_addr[2][2];
        #pragma unroll
        for (int b = 0; b < 2; b++)
            #pragma unroll
            for (int mt = 0; mt < 2; mt++)
                a_addr[b][mt] = sbase + OFF_A + b * ABUF +
                                (mbase + mt * 16 + arow) * RSTRIDE + acolb;
        const float b2v = __ldg(b2);

        BAR_ARRIVE(BAR_EMPTY0 + 0, 512);
        BAR_ARRIVE(BAR_EMPTY0 + 1, 512);

        int t = blockIdx.x;
        int it = 0;
        while (t < ntiles) {
            const int b = it & 1;
            BAR_SYNC(BAR_FULL0 + b, 512);

            float d[2][8][4];
            #pragma unroll
            for (int mt = 0; mt < 2; mt++)
                #pragma unroll
                for (int n = 0; n < 8; n++)
                    d[mt][n][0] = d[mt][n][1] = d[mt][n][2] = d[mt][n][3] = 0.0f;

            #pragma unroll 2
            for (int kk = 0; kk < 16; kk++) {
                uint32_t a0[2], a1[2], a2[2], a3[2];
                #pragma unroll
                for (int mt = 0; mt < 2; mt++)
                    ldmatrix_x4(a0[mt], a1[mt], a2[mt], a3[mt], a_addr[b][mt] + kk * 32);
                uint32_t bf[4][4];
                #pragma unroll
                for (int pr = 0; pr < 4; pr++)
                    ldmatrix_x4(bf[pr][0], bf[pr][1], bf[pr][2], bf[pr][3],
                                b_addr + pr * 16 * RSTRIDE + kk * 32);
                #pragma unroll
                for (int mt = 0; mt < 2; mt++)
                    #pragma unroll
                    for (int pr = 0; pr < 4; pr++) {
                        mma_f16(d[mt][2 * pr],     a0[mt], a1[mt], a2[mt], a3[mt],
                                bf[pr][0], bf[pr][1]);
                        mma_f16(d[mt][2 * pr + 1], a0[mt], a1[mt], a2[mt], a3[mt],
                                bf[pr][2], bf[pr][3]);
                    }
            }

            // All LDSM results consumed by issued MMAs -> SMEM reads of buf b done.
            // Release the buffer BEFORE the epilogue.
            BAR_ARRIVE(BAR_EMPTY0 + b, 512);

            // ---- epilogue: z = s1*G + s0*c1 + (c2+b1), ELU, dot(W2) ----
            const int sslot = (it & 3) * 128;      // sS is 4-deep: safe vs producer reuse
            float p[2][2];
            #pragma unroll
            for (int mt = 0; mt < 2; mt++) {
                const int rA = mbase + mt * 16 + (lane >> 2);
                const float2 SA = sS[sslot + rA];
                const float2 SB = sS[sslot + rA + 8];
                float p0 = 0.0f, p1 = 0.0f;
                #pragma unroll
                for (int n = 0; n < 8; n++) {
                    const int j0 = jbase + n * 8 + (lane & 3) * 2;
                    const float2 C0 = sC[j0];
                    const float2 C1 = sC[j0 + 1];
                    const float2 W2p = sw2v[j0 >> 1];
                    float v;
                    v = fmaf(SA.y, d[mt][n][0], fmaf(SA.x, C0.x, C0.y));
                    v = v > 0.0f ? v : (__expf(v) - 1.0f); p0 = fmaf(v, W2p.x, p0);
                    v = fmaf(SA.y, d[mt][n][1], fmaf(SA.x, C1.x, C1.y));
                    v = v > 0.0f ? v : (__expf(v) - 1.0f); p0 = fmaf(v, W2p.y, p0);
                    v = fmaf(SB.y, d[mt][n][2], fmaf(SB.x, C0.x, C0.y));
                    v = v > 0.0f ? v : (__expf(v) - 1.0f); p1 = fmaf(v, W2p.x, p1);
                    v = fmaf(SB.y, d[mt][n][3], fmaf(SB.x, C1.x, C1.y));
                    v = v > 0.0f ? v : (__expf(v) - 1.0f); p1 = fmaf(v, W2p.y, p1);
                }
                p0 += __shfl_xor_sync(0xffffffffu, p0, 1);
                p0 += __shfl_xor_sync(0xffffffffu, p0, 2);
                p1 += __shfl_xor_sync(0xffffffffu, p1, 1);
                p1 += __shfl_xor_sync(0xffffffffu, p1, 2);
                p[mt][0] = p0;
                p[mt][1] = p1;
            }

            if ((cw & 1) == 1 && (lane & 3) == 0) {
                #pragma unroll
                for (int mt = 0; mt < 2; mt++) {
                    const int r0 = mbase + mt * 16 + (lane >> 2);
                    pbuf[b * 128 + r0]     = p[mt][0];
                    pbuf[b * 128 + r0 + 8] = p[mt][1];
                }
            }
            BAR_SYNC(BAR_CONS, 256);
            if ((cw & 1) == 0 && (lane & 3) == 0) {
                const int ebase = t * M_TILE;
                #pragma unroll
                for (int mt = 0; mt < 2; mt++) {
                    const int r0 = mbase + mt * 16 + (lane >> 2);
                    const int e0 = ebase + r0;
                    const int e1 = e0 + 8;
                    if (e0 < E) out[e0] = p[mt][0] + pbuf[b * 128 + r0] + b2v;
                    if (e1 < E) out[e1] = p[mt][1] + pbuf[b * 128 + r0 + 8] + b2v;
                }
            }
            t += gridDim.x;
            it++;
        }
    }
}

extern "C" void kernel_launch(void* const* d_in, const int* in_sizes, int n_in,
                              void* d_out, int out_size)
{
    const float* x     = (const float*)d_in[0];
    const int*   src   = (const int*)  d_in[1];
    const int*   dst   = (const int*)  d_in[2];
    const float* a     = (const float*)d_in[3];
    const float* W1    = (const float*)d_in[4];
    const float* b1    = (const float*)d_in[5];
    const float* W2    = (const float*)d_in[6];
    const float* b2    = (const float*)d_in[7];
    const float* gamma = (const float*)d_in[8];
    const float* beta  = (const float*)d_in[9];
    float* out = (float*)d_out;
    const int E = in_sizes[1];

    cudaFuncSetAttribute(edge_mlp_ws_kernel,
                         cudaFuncAttributeMaxDynamicSharedMemorySize, SMEM_TOTAL);
    edge_mlp_ws_kernel<<<148, TPB, SMEM_TOTAL>>>(x, src, dst, a, W1, b1, W2, b2,
                                                 gamma, beta, out, E);
}

// round 16
// speedup vs baseline: 6.0404x; 1.0444x over previous
#include <cuda_runtime.h>
#include <cuda_fp16.h>
#include <cstdint>
#include <cstring>

#define DEV __device__ __forceinline__

DEV uint32_t smem_u32(const void* p) {
    uint32_t a;
    asm("{ .reg .u64 t; cvta.to.shared.u64 t, %1; cvt.u32.u64 %0, t; }" : "=r"(a) : "l"(p));
    return a;
}

DEV void ldmatrix_x4(uint32_t& r0, uint32_t& r1, uint32_t& r2, uint32_t& r3, uint32_t addr) {
    asm volatile("ldmatrix.sync.aligned.m8n8.x4.shared.b16 {%0,%1,%2,%3}, [%4];"
                 : "=r"(r0), "=r"(r1), "=r"(r2), "=r"(r3) : "r"(addr));
}

DEV void mma_f16(float* d, uint32_t a0, uint32_t a1, uint32_t a2, uint32_t a3,
                 uint32_t b0, uint32_t b1) {
    asm volatile("mma.sync.aligned.m16n8k16.row.col.f32.f16.f16.f32 "
                 "{%0,%1,%2,%3}, {%4,%5,%6,%7}, {%8,%9}, {%0,%1,%2,%3};"
                 : "+f"(d[0]), "+f"(d[1]), "+f"(d[2]), "+f"(d[3])
                 : "r"(a0), "r"(a1), "r"(a2), "r"(a3), "r"(b0), "r"(b1));
}

DEV uint32_t pack_h2(float a, float b) {
    __half2 h2 = __float22half2_rn(make_float2(a, b));
    uint32_t r;
    memcpy(&r, &h2, 4);
    return r;
}

DEV uint32_t mulh2(uint32_t h, __half2 s) {
    __half2 v;
    memcpy(&v, &h, 4);
    v = __hmul2(v, s);
    uint32_t r;
    memcpy(&r, &v, 4);
    return r;
}

#define BAR_SYNC(id, cnt)   asm volatile("bar.sync %0, %1;"   :: "r"(id), "r"(cnt) : "memory")
#define BAR_ARRIVE(id, cnt) asm volatile("bar.arrive %0, %1;" :: "r"(id), "r"(cnt) : "memory")
#define MEMBAR_CTA()        asm volatile("membar.cta;" ::: "memory")

constexpr int TPB    = 512;     // 16 warps: 8 producers + 8 consumers
constexpr int M_TILE = 128;
constexpr float LN_EPS = 1e-5f;

constexpr int KK_STEPS = 17;                     // 272 = 256 + 16 ext
constexpr int RSTRIDE = 560;                     // 272 fp16 = 544B + 16 pad (35x16B, conflict-free)
constexpr int ABUF = 128 * RSTRIDE;              // 71680 per buffer

// SMEM layout (bytes)
constexpr int OFF_W    = 0;                      // (gamma*W1)^T + ext, fp16: 128 x 560 = 71680
constexpr int OFF_A    = OFF_W + ABUF;           // A dbl-buf: 2 x 71680 = 143360
constexpr int OFF_PB   = OFF_A + 2 * ABUF;       // pbuf: 2 x 128 f = 1024
constexpr int OFF_SW2  = OFF_PB + 1024;          // W2 128 f
constexpr int OFF_G    = OFF_SW2 + 512;          // gamma 256 f
constexpr int OFF_BETA = OFF_G + 1024;           // beta 256 f
constexpr int OFF_SB1  = OFF_BETA + 1024;        // b1 128 f
constexpr int SMEM_TOTAL = OFF_SB1 + 512;        // 219136

constexpr int BAR_FULL0  = 1;
constexpr int BAR_EMPTY0 = 3;
constexpr int BAR_CONS   = 5;

// Load all 16 edges' metadata for this warp in one coalesced round.
DEV void loadMeta(int tbase, int E, int lane,
                  const int* __restrict__ src, const int* __restrict__ dst,
                  const float* __restrict__ a, int& ms, float& ma)
{
    int ei = min(tbase + (lane & 15), E - 1);
    ms = (lane < 16) ? __ldg(src + ei) : __ldg(dst + ei);
    ma = __ldg(a + ei);
}

DEV void loadVec(int ms, int lane, const float* __restrict__ x, int e0,
                 float4* vs, float4* vd)
{
    int si0 = __shfl_sync(0xffffffffu, ms, e0);
    int di0 = __shfl_sync(0xffffffffu, ms, 16 + e0);
    int si1 = __shfl_sync(0xffffffffu, ms, e0 + 1);
    int di1 = __shfl_sync(0xffffffffu, ms, 17 + e0);
    vs[0] = __ldg(reinterpret_cast<const float4*>(x + (size_t)si0 * 128) + lane);
    vd[0] = __ldg(reinterpret_cast<const float4*>(x + (size_t)di0 * 128) + lane);
    vs[1] = __ldg(reinterpret_cast<const float4*>(x + (size_t)si1 * 128) + lane);
    vd[1] = __ldg(reinterpret_cast<const float4*>(x + (size_t)di1 * 128) + lane);
}

__global__ __launch_bounds__(TPB, 1)
void edge_mlp_ws_kernel(const float* __restrict__ x,
                        const int*   __restrict__ src,
                        const int*   __restrict__ dst,
                        const float* __restrict__ a,
                        const float* __restrict__ W1,
                        const float* __restrict__ b1,
                        const float* __restrict__ W2,
                        const float* __restrict__ b2,
                        const float* __restrict__ gamma,
                        const float* __restrict__ beta,
                        float* __restrict__ out,
                        int E)
{
    extern __shared__ char smem[];
    float*  pbuf = reinterpret_cast<float*>(smem + OFF_PB);
    float*  sw2  = reinterpret_cast<float*>(smem + OFF_SW2);
    float2* sw2v = reinterpret_cast<float2*>(smem + OFF_SW2);
    float*  sg   = reinterpret_cast<float*>(smem + OFF_G);
    float*  sbt  = reinterpret_cast<float*>(smem + OFF_BETA);
    float*  sb1  = reinterpret_cast<float*>(smem + OFF_SB1);

    const int tid  = threadIdx.x;
    const int warp = tid >> 5;
    const int lane = tid & 31;
    const uint32_t sbase = smem_u32(smem);

    // ---- params
    for (int i = tid; i < 256; i += TPB) { sg[i] = __ldg(gamma + i); sbt[i] = __ldg(beta + i); }
    if (tid < 128) { sb1[tid] = __ldg(b1 + tid); sw2[tid] = __ldg(W2 + tid); }
    __syncthreads();

    // ---- Stage W~ = gamma_k * W1[k][j] (fp16) at row j, col k
    for (int idx = tid; idx < 256 * 128; idx += TPB) {
        int k = idx >> 7, j = idx & 127;
        *reinterpret_cast<__half*>(smem + OFF_W + j * RSTRIDE + k * 2) =
            __float2half_rn(sg[k] * __ldg(W1 + idx));
    }
    // ---- W ext cols: k=256 -> c1_j; k=257 -> c2_j + b1_j; k=258..271 -> 0
    if (tid < 128) {
        float c1 = 0.0f, c2 = 0.0f;
        for (int k = 0; k < 256; k++) {
            float w = __ldg(W1 + k * 128 + tid);
            c1 = fmaf(sg[k],  w, c1);
            c2 = fmaf(sbt[k], w, c2);
        }
        char* Wr = smem + OFF_W + tid * RSTRIDE;
        *reinterpret_cast<uint32_t*>(Wr + 512) = pack_h2(c1, c2 + sb1[tid]);
        *reinterpret_cast<uint32_t*>(Wr + 516) = 0;
        *reinterpret_cast<uint64_t*>(Wr + 520) = 0ULL;
        *reinterpret_cast<uint64_t*>(Wr + 528) = 0ULL;
        *reinterpret_cast<uint64_t*>(Wr + 536) = 0ULL;
    }
    // ---- Zero A ext bytes [520,544) for all rows, both buffers (written once)
    for (int i = tid; i < 2 * 128 * 3; i += TPB) {
        int b  = i / (128 * 3);
        int r  = (i / 3) % 128;
        int q  = i % 3;
        *reinterpret_cast<uint64_t*>(smem + OFF_A + b * ABUF + r * RSTRIDE + 520 + q * 8) = 0ULL;
    }
    __syncthreads();

    const int ntiles = (E + M_TILE - 1) / M_TILE;

    if (warp < 8) {
        // ======================= PRODUCER (8 warps, 2/SMSP) =======================
        const int pw = warp;            // rows pw*16 .. pw*16+15 of each tile

        int   ms, msN;
        float ma, maN;
        float4 vs[2][2], vd[2][2];

        int t = blockIdx.x;
        if (t < ntiles) {
            loadMeta(t * M_TILE + pw * 16, E, lane, src, dst, a, ms, ma);
            loadVec(ms, lane, x, 0, vs[0], vd[0]);
        }

        int it = 0;
        while (t < ntiles) {
            const int b = it & 1;
            BAR_SYNC(BAR_EMPTY0 + b, 512);

            char* Ab = smem + OFF_A + b * ABUF;
            const int tn = t + gridDim.x;
            loadMeta((tn < ntiles ? tn : t) * M_TILE + pw * 16, E, lane,
                     src, dst, a, msN, maN);

            #pragma unroll
            for (int p = 0; p < 8; p++) {          // 8 pairs of edges
                const int cur = p & 1, nxt = cur ^ 1;
                if (p < 7) loadVec(ms,  lane, x, (p + 1) * 2, vs[nxt], vd[nxt]);
                else       loadVec(msN, lane, x, 0,           vs[nxt], vd[nxt]);

                #pragma unroll
                for (int e = 0; e < 2; e++) {
                    const float4 s4 = vs[cur][e], d4 = vd[cur][e];
                    const int row = pw * 16 + p * 2 + e;
                    char* Ah = Ab + row * RSTRIDE;

                    // pack raw h early (independent of reduction)
                    uint32_t h0 = pack_h2(s4.x, s4.y);
                    uint32_t h1 = pack_h2(s4.z, s4.w);
                    uint32_t h2 = pack_h2(d4.x, d4.y);
                    uint32_t h3 = pack_h2(d4.z, d4.w);

                    // raw moments
                    float sum = (s4.x + s4.y) + (s4.z + s4.w) + (d4.x + d4.y) + (d4.z + d4.w);
                    float sq = s4.x * s4.x;
                    sq = fmaf(s4.y, s4.y, sq); sq = fmaf(s4.z, s4.z, sq); sq = fmaf(s4.w, s4.w, sq);
                    sq = fmaf(d4.x, d4.x, sq); sq = fmaf(d4.y, d4.y, sq);
                    sq = fmaf(d4.z, d4.z, sq); sq = fmaf(d4.w, d4.w, sq);
                    #pragma unroll
                    for (int o = 16; o > 0; o >>= 1) {
                        sum += __shfl_xor_sync(0xffffffffu, sum, o);
                        sq  += __shfl_xor_sync(0xffffffffu, sq,  o);
                    }
                    const float mu  = sum * (1.0f / 256.0f);
                    const float var = fmaf(-mu, mu, sq * (1.0f / 256.0f));
                    const float ae  = __shfl_sync(0xffffffffu, ma, p * 2 + e);
                    const float s1  = ae * rsqrtf(fmaf(ae * ae, var, LN_EPS));
                    const float s0  = -mu * s1;

                    // scale packed h by s1 (fp16 mul) and store
                    const __half2 sh = __float2half2_rn(s1);
                    h0 = mulh2(h0, sh); h1 = mulh2(h1, sh);
                    h2 = mulh2(h2, sh); h3 = mulh2(h3, sh);
                    *reinterpret_cast<uint64_t*>(Ah + lane * 8)       = (uint64_t)h0 | ((uint64_t)h1 << 32);
                    *reinterpret_cast<uint64_t*>(Ah + 256 + lane * 8) = (uint64_t)h2 | ((uint64_t)h3 << 32);
                    // ext word: k256=s0, k257=1, k258..259=0 (260..271 pre-zeroed)
                    if (lane == 0)
                        *reinterpret_cast<uint64_t*>(Ah + 512) = (uint64_t)pack_h2(s0, 1.0f);
                }
            }
            ms = msN; ma = maN;
            MEMBAR_CTA();
            BAR_ARRIVE(BAR_FULL0 + b, 512);
            t = tn;
            it++;
        }
    } else {
        // ======================= CONSUMER (8 warps, 2/SMSP) =======================
        const int cw = warp - 8;
        const int mbase = (cw >> 1) * 32;      // 2 m16-subtiles per warp
        const int jbase = (cw & 1) * 64;

        const int arow  = (lane & 7) + ((lane >> 3) & 1) * 8;
        const int acolb = ((lane >> 4) & 1) * 16;
        const int brow  = (lane & 7) + ((lane >> 4) & 1) * 8;
        const int bkb   = ((lane >> 3) & 1) * 16;

        const uint32_t b_addr = sbase + OFF_W + (jbase + brow) * RSTRIDE + bkb;
        uint32_t a_addr[2][2];
        #pragma unroll
        for (int b = 0; b < 2; b++)
            #pragma unroll
            for (int mt = 0; mt < 2; mt++)
                a_addr[b][mt] = sbase + OFF_A + b * ABUF +
                                (mbase + mt * 16 + arow) * RSTRIDE + acolb;
        const float b2v = __ldg(b2);

        BAR_ARRIVE(BAR_EMPTY0 + 0, 512);
        BAR_ARRIVE(BAR_EMPTY0 + 1, 512);

        int t = blockIdx.x;
        int it = 0;
        while (t < ntiles) {
            const int b = it & 1;
            BAR_SYNC(BAR_FULL0 + b, 512);

            float d[2][8][4];
            #pragma unroll
            for (int mt = 0; mt < 2; mt++)
                #pragma unroll
                for (int n = 0; n < 8; n++)
                    d[mt][n][0] = d[mt][n][1] = d[mt][n][2] = d[mt][n][3] = 0.0f;

            #pragma unroll 2
            for (int kk = 0; kk < KK_STEPS; kk++) {
                uint32_t a0[2], a1[2], a2[2], a3[2];
                #pragma unroll
                for (int mt = 0; mt < 2; mt++)
                    ldmatrix_x4(a0[mt], a1[mt], a2[mt], a3[mt], a_addr[b][mt] + kk * 32);
                uint32_t bf[4][4];
                #pragma unroll
                for (int pr = 0; pr < 4; pr++)
                    ldmatrix_x4(bf[pr][0], bf[pr][1], bf[pr][2], bf[pr][3],
                                b_addr + pr * 16 * RSTRIDE + kk * 32);
                #pragma unroll
                for (int mt = 0; mt < 2; mt++)
                    #pragma unroll
                    for (int pr = 0; pr < 4; pr++) {
                        mma_f16(d[mt][2 * pr],     a0[mt], a1[mt], a2[mt], a3[mt],
                                bf[pr][0], bf[pr][1]);
                        mma_f16(d[mt][2 * pr + 1], a0[mt], a1[mt], a2[mt], a3[mt],
                                bf[pr][2], bf[pr][3]);
                    }
            }

            // All LDSM results consumed -> release buffer before epilogue.
            BAR_ARRIVE(BAR_EMPTY0 + b, 512);

            // ---- epilogue: d == z already; ELU + dot(W2) ----
            float p[2][2];
            #pragma unroll
            for (int mt = 0; mt < 2; mt++) {
                float p0 = 0.0f, p1 = 0.0f;
                #pragma unroll
                for (int n = 0; n < 8; n++) {
                    const int j0 = jbase + n * 8 + (lane & 3) * 2;
                    const float2 W2p = sw2v[j0 >> 1];
                    float v;
                    v = d[mt][n][0]; v = v > 0.0f ? v : (__expf(v) - 1.0f); p0 = fmaf(v, W2p.x, p0);
                    v = d[mt][n][1]; v = v > 0.0f ? v : (__expf(v) - 1.0f); p0 = fmaf(v, W2p.y, p0);
                    v = d[mt][n][2]; v = v > 0.0f ? v : (__expf(v) - 1.0f); p1 = fmaf(v, W2p.x, p1);
                    v = d[mt][n][3]; v = v > 0.0f ? v : (__expf(v) - 1.0f); p1 = fmaf(v, W2p.y, p1);
                }
                p0 += __shfl_xor_sync(0xffffffffu, p0, 1);
                p0 += __shfl_xor_sync(0xffffffffu, p0, 2);
                p1 += __shfl_xor_sync(0xffffffffu, p1, 1);
                p1 += __shfl_xor_sync(0xffffffffu, p1, 2);
                p[mt][0] = p0;
                p[mt][1] = p1;
            }

            if ((cw & 1) == 1 && (lane & 3) == 0) {
                #pragma unroll
                for (int mt = 0; mt < 2; mt++) {
                    const int r0 = mbase + mt * 16 + (lane >> 2);
                    pbuf[b * 128 + r0]     = p[mt][0];
                    pbuf[b * 128 + r0 + 8] = p[mt][1];
                }
            }
            BAR_SYNC(BAR_CONS, 256);
            if ((cw & 1) == 0 && (lane & 3) == 0) {
                const int ebase = t * M_TILE;
                #pragma unroll
                for (int mt = 0; mt < 2; mt++) {
                    const int r0 = mbase + mt * 16 + (lane >> 2);
                    const int e0 = ebase + r0;
                    const int e1 = e0 + 8;
                    if (e0 < E) out[e0] = p[mt][0] + pbuf[b * 128 + r0] + b2v;
                    if (e1 < E) out[e1] = p[mt][1] + pbuf[b * 128 + r0 + 8] + b2v;
                }
            }
            t += gridDim.x;
            it++;
        }
    }
}

extern "C" void kernel_launch(void* const* d_in, const int* in_sizes, int n_in,
                              void* d_out, int out_size)
{
    const float* x     = (const float*)d_in[0];
    const int*   src   = (const int*)  d_in[1];
    const int*   dst   = (const int*)  d_in[2];
    const float* a     = (const float*)d_in[3];
    const float* W1    = (const float*)d_in[4];
    const float* b1    = (const float*)d_in[5];
    const float* W2    = (const float*)d_in[6];
    const float* b2    = (const float*)d_in[7];
    const float* gamma = (const float*)d_in[8];
    const float* beta  = (const float*)d_in[9];
    float* out = (float*)d_out;
    const int E = in_sizes[1];

    cudaFuncSetAttribute(edge_mlp_ws_kernel,
                         cudaFuncAttributeMaxDynamicSharedMemorySize, SMEM_TOTAL);
    edge_mlp_ws_kernel<<<148, TPB, SMEM_TOTAL>>>(x, src, dst, a, W1, b1, W2, b2,
                                                 gamma, beta, out, E);
}